// round 7
// baseline (speedup 1.0000x reference)
#include <cuda_runtime.h>
#include <cuda_fp16.h>
#include <math.h>
#include <stdint.h>

#define Bn 4096
#define HSLOT ((size_t)Bn * 512)
#define STAGE_BYTES 36864
#define SMEM_BYTES (2 * STAGE_BYTES)

// fused-kernel smem layout (bytes)
#define FSM_HC 0            // 32 rows x 520 halfs (1040B pitch) = 33280
#define FSM_HB 33280        // 32 x 512 halfs = 32768
#define FSM_HG 66048        // 32768
#define FSM_B  98816        // 2 x 65536 (B tile: 512 n-rows x 128B, XOR-swizzled)
#define FSM_TOTAL 229888

// ---------------- device scratch ----------------
__device__ __half g_Ah[(size_t)17 * HSLOT];         // slot j+1 holds h_j (fp16); slot 0 unused
__device__ __half g_APRE[(size_t)65536 * 64];       // [b*16+t][x(63)|t(1)]
__device__ __half g_WTb[(size_t)2560 * 512];        // [Uh | Wa], n-major
__device__ __half g_WPRE[(size_t)2560 * 64];        // [WxWt-fold | WxT], n-major
__device__ __half g_WT2[1024 * 512];                // [Wb | Wg]
__device__ __half g_WT3[512 * 512];                 // We
__device__ __half g_WTh[256 * 512];                 // W1
__device__ __half g_ZX16[(size_t)16 * Bn * 2048];   // x@Wx + b + t*Wt
__device__ __half g_TG16[(size_t)16 * Bn * 512];    // full Tg gate (precomputed)
__device__ __half g_MEMA16[(size_t)15 * HSLOT];     // slot j: h_j @ Wa
__device__ __half g_Z16[(size_t)Bn * 2048];         // h@Uh for current step
__device__ float g_C[(size_t)Bn * 512];
__device__ float g_HD1[(size_t)Bn * 256];
__device__ float g_HD2[(size_t)Bn * 32];
__device__ float g_s[512];
__device__ float g_sA[512];

// ---------------- helpers ----------------
__device__ __forceinline__ float tanh_app(float x) {
    float y; asm("tanh.approx.f32 %0, %1;" : "=f"(y) : "f"(x)); return y;
}
__device__ __forceinline__ float sigmf(float x) {
    return __fdividef(1.f, 1.f + __expf(-x));
}
__device__ __forceinline__ uint32_t smem_u32(const void* p) {
    uint32_t a;
    asm("{ .reg .u64 t; cvta.to.shared.u64 t, %1; cvt.u32.u64 %0, t; }" : "=r"(a) : "l"(p));
    return a;
}
__device__ __forceinline__ void ldm4(uint32_t* r, uint32_t a) {
    asm volatile("ldmatrix.sync.aligned.m8n8.x4.shared.b16 {%0,%1,%2,%3}, [%4];"
                 : "=r"(r[0]), "=r"(r[1]), "=r"(r[2]), "=r"(r[3]) : "r"(a));
}
__device__ __forceinline__ void mma16816(float* c, const uint32_t* a, uint32_t b0, uint32_t b1) {
    asm volatile("mma.sync.aligned.m16n8k16.row.col.f32.f16.f16.f32 "
                 "{%0,%1,%2,%3}, {%4,%5,%6,%7}, {%8,%9}, {%0,%1,%2,%3};"
                 : "+f"(c[0]), "+f"(c[1]), "+f"(c[2]), "+f"(c[3])
                 : "r"(a[0]), "r"(a[1]), "r"(a[2]), "r"(a[3]), "r"(b0), "r"(b1));
}
__device__ __forceinline__ void cp16(uint32_t saddr, const void* gptr) {
    asm volatile("cp.async.cg.shared.global [%0], [%1], 16;"
                 :: "r"(saddr), "l"(__cvta_generic_to_global(gptr)) : "memory");
}
__device__ __forceinline__ void cp_commit() {
    asm volatile("cp.async.commit_group;" ::: "memory");
}

// ---------------- prep kernels ----------------
__global__ void prep_weights(const float* __restrict__ Uh, const float* __restrict__ Wx,
                             const float* __restrict__ Wt, const float* __restrict__ Wa,
                             const float* __restrict__ WxT, const float* __restrict__ Wb,
                             const float* __restrict__ Wg, const float* __restrict__ We,
                             const float* __restrict__ W1) {
    int stride = gridDim.x * blockDim.x;
    int t0 = blockIdx.x * blockDim.x + threadIdx.x;
    for (int i = t0; i < 2560 * 512; i += stride) {
        int n = i >> 9, k = i & 511;
        float w = (n < 2048) ? Uh[(size_t)k * 2048 + n] : Wa[(size_t)k * 512 + (n - 2048)];
        g_WTb[i] = __float2half(w);
    }
    for (int i = t0; i < 2560 * 64; i += stride) {
        int n = i >> 6, k = i & 63;
        float w;
        if (k < 63) w = (n < 2048) ? Wx[(size_t)k * 2048 + n] : WxT[(size_t)k * 512 + (n - 2048)];
        else        w = (n < 1536) ? Wt[n] : 0.f;
        g_WPRE[i] = __float2half(w);
    }
    for (int i = t0; i < 1024 * 512; i += stride) {
        int n = i >> 9, k = i & 511;
        float w = (n < 512) ? Wb[(size_t)k * 512 + n] : Wg[(size_t)k * 512 + (n - 512)];
        g_WT2[i] = __float2half(w);
    }
    for (int i = t0; i < 512 * 512; i += stride) {
        int n = i >> 9, k = i & 511;
        g_WT3[i] = __float2half(We[(size_t)k * 512 + n]);
    }
    for (int i = t0; i < 256 * 512; i += stride) {
        int n = i >> 9, k = i & 511;
        g_WTh[i] = __float2half(W1[(size_t)k * 256 + n]);
    }
}

__global__ void prep_s(const float* __restrict__ init_proj) {
    int h = threadIdx.x;
    float s = 0.f;
    for (int f = 0; f < 64; ++f) s += init_proj[f * 512 + h];
    g_s[h] = s;
}

__global__ void prep_sA(const float* __restrict__ Wa) {
    int h = threadIdx.x;
    float acc = 0.f;
    for (int k = 0; k < 512; ++k) acc += g_s[k] * Wa[k * 512 + h];
    g_sA[h] = acc;
}

__global__ void prep_A(const float* __restrict__ inp) {
    int stride = gridDim.x * blockDim.x;
    int t0 = blockIdx.x * blockDim.x + threadIdx.x;
    for (int i = t0; i < 65536 * 64; i += stride) {
        int r = i >> 6, k = i & 63;
        float v = (k < 63) ? inp[(size_t)r * 64 + 1 + k] : inp[(size_t)r * 64];
        g_APRE[i] = __float2half(v);
    }
}

// ---------------- fp16 HMMA GEMM (MODE 1: recurrent, 5: input pre-GEMM, 4: head) ----------------
// block 128x128, 8 warps of 64x32, k-chunk 64, cp.async double buffer
// MODE 1: N=2560 [Uh|Wa]: c<2048 -> g_Z16 (raw fp16); else -> o2h (MEMA slot)
// MODE 5: N=2560 [WxWt|WxT]: rows r=(b*16+t); c<2048 -> g_ZX16=acc+b; else -> g_TG16=Tg
// MODE 4: N=256 W1: o0 = relu(acc+e0)
template <int MODE>
__global__ __launch_bounds__(256, 2)
void mma_gemm(const __half* __restrict__ A, int lda, int K,
              const __half* __restrict__ Bh,
              const float* __restrict__ e0, float* __restrict__ o0,
              __half* __restrict__ o2h,
              const float* __restrict__ inp, const float* __restrict__ WtT,
              const float* __restrict__ bT) {
    extern __shared__ char smem[];
    uint32_t sb = smem_u32(smem);
    const int tid = threadIdx.x;
    const int lane = tid & 31, wid = tid >> 5;
    const int wm = wid & 1, wn = wid >> 1;
    const int gid = lane >> 2, tq = lane & 3;
    const int m0 = blockIdx.y * 128, n0 = blockIdx.x * 128;

    const int kch = K >> 6;

    float acc[4][4][4];
    #pragma unroll
    for (int a = 0; a < 4; ++a)
        #pragma unroll
        for (int b2 = 0; b2 < 4; ++b2)
            #pragma unroll
            for (int c = 0; c < 4; ++c) acc[a][b2][c] = 0.f;

    auto copy_chunk = [&](int ch, int s) {
        int kc = ch << 6;
        uint32_t base = sb + s * STAGE_BYTES;
        #pragma unroll
        for (int i = 0; i < 4; ++i) {
            int lin = tid + (i << 8);
            int r = lin >> 3;
            int c16 = (lin & 7) << 4;
            cp16(base + r * 144 + c16,
                 (const char*)(A + (size_t)(m0 + r) * lda + kc) + c16);
            cp16(base + 18432 + r * 144 + c16,
                 (const char*)(Bh + (size_t)(n0 + r) * K + kc) + c16);
        }
    };

    copy_chunk(0, 0);
    cp_commit();

    const int arow = wm * 64 + (lane & 15);
    const int acol = (lane >> 4) << 4;
    const int brow = wn * 32 + (lane & 7) + ((lane >> 4) << 3);
    const int bcol = ((lane >> 3) & 1) << 4;

    for (int ch = 0; ch < kch; ++ch) {
        if (ch + 1 < kch) {
            copy_chunk(ch + 1, (ch + 1) & 1);
            cp_commit();
            asm volatile("cp.async.wait_group 1;" ::: "memory");
        } else {
            asm volatile("cp.async.wait_group 0;" ::: "memory");
        }
        __syncthreads();

        uint32_t abase = sb + (ch & 1) * STAGE_BYTES;
        uint32_t bbase = abase + 18432;
        #pragma unroll
        for (int k16 = 0; k16 < 4; ++k16) {
            int kb = k16 << 5;
            uint32_t bf[2][4];
            #pragma unroll
            for (int ni2 = 0; ni2 < 2; ++ni2)
                ldm4(bf[ni2], bbase + (brow + ni2 * 16) * 144 + kb + bcol);
            uint32_t af[4][4];
            #pragma unroll
            for (int mi = 0; mi < 4; ++mi)
                ldm4(af[mi], abase + (arow + mi * 16) * 144 + kb + acol);
            #pragma unroll
            for (int ni2 = 0; ni2 < 2; ++ni2)
                #pragma unroll
                for (int mi = 0; mi < 4; ++mi) {
                    mma16816(acc[mi][ni2 * 2],     af[mi], bf[ni2][0], bf[ni2][1]);
                    mma16816(acc[mi][ni2 * 2 + 1], af[mi], bf[ni2][2], bf[ni2][3]);
                }
        }
        __syncthreads();
    }

    auto epi = [&](int m, int c, float x, float y) {
        if (MODE == 1) {
            if (c < 2048) {
                *(__half2*)(g_Z16 + (size_t)m * 2048 + c) =
                    __floats2half2_rn(x, y);
            } else {
                *(__half2*)(o2h + (size_t)m * 512 + (c - 2048)) =
                    __floats2half2_rn(x, y);
            }
        } else if (MODE == 5) {
            int b_ = m >> 4, t_ = m & 15;
            size_t zr = (size_t)t_ * Bn + b_;
            if (c < 2048) {
                *(__half2*)(g_ZX16 + zr * 2048 + c) =
                    __floats2half2_rn(x + e0[c], y + e0[c + 1]);
            } else {
                int j = c - 2048;
                float tv = inp[(size_t)m * 64];
                float t0v = sigmf(x + sigmf(tv * WtT[j]) + bT[j]);
                float t1v = sigmf(y + sigmf(tv * WtT[j + 1]) + bT[j + 1]);
                *(__half2*)(g_TG16 + zr * 512 + j) = __floats2half2_rn(t0v, t1v);
            }
        } else {  // MODE 4
            *(float2*)(o0 + (size_t)m * 256 + c) =
                make_float2(fmaxf(x + e0[c], 0.f), fmaxf(y + e0[c + 1], 0.f));
        }
    };

    #pragma unroll
    for (int mi = 0; mi < 4; ++mi) {
        #pragma unroll
        for (int ni = 0; ni < 4; ++ni) {
            float* cc = acc[mi][ni];
            int m = m0 + wm * 64 + mi * 16 + gid;
            int c = n0 + wn * 32 + ni * 8 + (tq << 1);
            epi(m, c, cc[0], cc[1]);
            epi(m + 8, c, cc[2], cc[3]);
        }
    }
}

// ---------------- fused per-step kernel: gates -> GEMM2 -> attention -> GEMM3 ----------------
// 32 rows per CTA, 128 CTAs, 8 warps. All intermediates in smem.
__global__ __launch_bounds__(256, 1)
void step_fused(int t, const float* __restrict__ va, const float* __restrict__ ba,
                const float* __restrict__ bhv) {
    extern __shared__ char sm[];
    uint32_t sb = smem_u32(sm);
    const int tid = threadIdx.x, lane = tid & 31, w = tid >> 5;
    const int m0 = blockIdx.x * 32;
    const int first = (t == 0);
    const int gid = lane >> 2, tq = lane & 3;

    __half* HCs = (__half*)(sm + FSM_HC);   // pitch 520 halfs; holds Hc then CX
    __half* HBs = (__half*)(sm + FSM_HB);   // pitch 512 halfs
    __half* HGs = (__half*)(sm + FSM_HG);   // pitch 512 halfs

    // ---- P0: gates + cell update ----
    {
        const __half* zx  = g_ZX16 + ((size_t)t * Bn + m0) * 2048;
        const __half* zh  = g_Z16 + (size_t)m0 * 2048;
        const __half* tgp = g_TG16 + ((size_t)t * Bn + m0) * 512;
        #pragma unroll 4
        for (int i = 0; i < 64; ++i) {
            int idx = tid + (i << 8);
            int m = idx >> 9, j = idx & 511;
            size_t zo = (size_t)m * 2048 + j;
            float zi = __half2float(zx[zo]);
            float zf = __half2float(zx[zo + 512]);
            float zog = __half2float(zx[zo + 1024]);
            float zc = __half2float(zx[zo + 1536]);
            if (!first) {
                zi  += __half2float(zh[zo]);
                zf  += __half2float(zh[zo + 512]);
                zog += __half2float(zh[zo + 1024]);
                zc  += __half2float(zh[zo + 1536]);
            }
            float tg = __half2float(tgp[(size_t)m * 512 + j]);
            float ig = sigmf(zi), fg = sigmf(zf), og = sigmf(zog), ch = tanh_app(zc);
            size_t ci = (size_t)(m0 + m) * 512 + j;
            float c = first ? (ig + tg) * ch : fmaf(fg, g_C[ci], (ig + tg) * ch);
            g_C[ci] = c;
            HCs[m * 520 + j] = __float2half(og * tanh_app(c));
        }
    }
    __syncthreads();

    // ---- B tile loader: 512 n-rows x 64 k, XOR-swizzled 128B pitch ----
    auto loadB = [&](const __half* W, int nbase, int kc, int buf) {
        uint32_t bb = sb + FSM_B + (buf << 16);
        #pragma unroll
        for (int i = 0; i < 16; ++i) {
            int lin = tid + (i << 8);
            int n = lin >> 3;
            int c16 = (lin & 7) << 4;
            cp16(bb + n * 128 + (c16 ^ ((n & 7) << 4)),
                 (const char*)(W + (size_t)(nbase + n) * 512 + kc) + c16);
        }
    };

    float acc[2][8][4];
    auto zero_acc = [&]() {
        #pragma unroll
        for (int a = 0; a < 2; ++a)
            #pragma unroll
            for (int b2 = 0; b2 < 8; ++b2)
                #pragma unroll
                for (int c = 0; c < 4; ++c) acc[a][b2][c] = 0.f;
    };

    // K=512 GEMM on A = HCs (32 x 512), warp w covers n in [64w, 64w+64)
    auto gemm512 = [&](const __half* W, int nbase) {
        loadB(W, nbase, 0, 0);
        cp_commit();
        for (int ch = 0; ch < 8; ++ch) {
            if (ch < 7) {
                loadB(W, nbase, (ch + 1) << 6, (ch + 1) & 1);
                cp_commit();
                asm volatile("cp.async.wait_group 1;" ::: "memory");
            } else {
                asm volatile("cp.async.wait_group 0;" ::: "memory");
            }
            __syncthreads();
            uint32_t bufb = sb + FSM_B + ((ch & 1) << 16);
            int kcb = ch << 7;   // byte offset of chunk in A rows (64 halfs = 128B)
            #pragma unroll
            for (int k16 = 0; k16 < 4; ++k16) {
                int kb = k16 << 5;
                uint32_t af[2][4];
                #pragma unroll
                for (int mi = 0; mi < 2; ++mi)
                    ldm4(af[mi], sb + FSM_HC + (mi * 16 + (lane & 15)) * 1040
                                 + kcb + kb + ((lane >> 4) << 4));
                #pragma unroll
                for (int ni2 = 0; ni2 < 4; ++ni2) {
                    uint32_t bf[4];
                    int brow = w * 64 + (lane & 7) + ((lane >> 4) << 3) + ni2 * 16;
                    ldm4(bf, bufb + brow * 128
                             + ((kb + (((lane >> 3) & 1) << 4)) ^ ((brow & 7) << 4)));
                    #pragma unroll
                    for (int mi = 0; mi < 2; ++mi) {
                        mma16816(acc[mi][ni2 * 2],     af[mi], bf[0], bf[1]);
                        mma16816(acc[mi][ni2 * 2 + 1], af[mi], bf[2], bf[3]);
                    }
                }
            }
            __syncthreads();
        }
    };

    // ---- P1: GEMM2 sweep 0 (HB = Hc@Wb + ba) ----
    zero_acc();
    gemm512(g_WT2, 0);
    #pragma unroll
    for (int mi = 0; mi < 2; ++mi)
        #pragma unroll
        for (int ni = 0; ni < 8; ++ni) {
            float* cc = acc[mi][ni];
            int m = mi * 16 + gid;
            int n = w * 64 + ni * 8 + (tq << 1);
            float b0 = ba[n], b1 = ba[n + 1];
            *(__half2*)(HBs + m * 512 + n) = __floats2half2_rn(cc[0] + b0, cc[1] + b1);
            *(__half2*)(HBs + (m + 8) * 512 + n) = __floats2half2_rn(cc[2] + b0, cc[3] + b1);
        }
    // ---- GEMM2 sweep 1 (HG = Hc@Wg) ----
    zero_acc();
    gemm512(g_WT2, 512);
    #pragma unroll
    for (int mi = 0; mi < 2; ++mi)
        #pragma unroll
        for (int ni = 0; ni < 8; ++ni) {
            float* cc = acc[mi][ni];
            int m = mi * 16 + gid;
            int n = w * 64 + ni * 8 + (tq << 1);
            *(__half2*)(HGs + m * 512 + n) = __floats2half2_rn(cc[0], cc[1]);
            *(__half2*)(HGs + (m + 8) * 512 + n) = __floats2half2_rn(cc[2], cc[3]);
        }
    __syncthreads();

    // ---- P2: attention (warp w owns rows 4w..4w+3) ----
    {
        float vaL[16], sL[16], sAL[16];
        #pragma unroll
        for (int i = 0; i < 16; ++i) {
            int h = lane + (i << 5);
            vaL[i] = va[h]; sL[i] = g_s[h]; sAL[i] = g_sA[h];
        }
        #pragma unroll 1
        for (int q = 0; q < 4; ++q) {
            int r = (w << 2) + q;
            int b = m0 + r;
            float hb[16];
            #pragma unroll
            for (int i = 0; i < 16; ++i)
                hb[i] = __half2float(HBs[r * 512 + lane + (i << 5)]);
            float ed[15];
            #pragma unroll
            for (int d = 0; d < 15; ++d) {
                int j = t - 15 + d;
                float sum = 0.f;
                if (j < 0) {
                    #pragma unroll
                    for (int i = 0; i < 16; ++i)
                        sum += vaL[i] * tanh_app(sAL[i] + hb[i]);
                } else {
                    const __half* ma = g_MEMA16 + (size_t)j * HSLOT + (size_t)b * 512;
                    #pragma unroll
                    for (int i = 0; i < 16; ++i)
                        sum += vaL[i] * tanh_app(__half2float(ma[lane + (i << 5)]) + hb[i]);
                }
                #pragma unroll
                for (int off = 16; off; off >>= 1)
                    sum += __shfl_xor_sync(0xffffffffu, sum, off);
                ed[d] = sum;
            }
            float mx = ed[0];
            #pragma unroll
            for (int d = 1; d < 15; ++d) mx = fmaxf(mx, ed[d]);
            float al[15], asum = 0.f;
            #pragma unroll
            for (int d = 0; d < 15; ++d) { al[d] = __expf(ed[d] - mx); asum += al[d]; }
            float inv = __fdividef(1.f, asum);
            float cx[16];
            #pragma unroll
            for (int i = 0; i < 16; ++i) cx[i] = 0.f;
            #pragma unroll
            for (int d = 0; d < 15; ++d) {
                int j = t - 15 + d;
                float a = al[d] * inv;
                if (j < 0) {
                    #pragma unroll
                    for (int i = 0; i < 16; ++i) cx[i] = fmaf(a, sL[i], cx[i]);
                } else {
                    const __half* mm = g_Ah + (size_t)(j + 1) * HSLOT + (size_t)b * 512;
                    #pragma unroll
                    for (int i = 0; i < 16; ++i)
                        cx[i] = fmaf(a, __half2float(mm[lane + (i << 5)]), cx[i]);
                }
            }
            #pragma unroll
            for (int i = 0; i < 16; ++i)
                HCs[r * 520 + lane + (i << 5)] = __float2half(cx[i]);
        }
    }

    // ---- P3: GEMM3 (h_new = tanh(CX@We + HG + bh)) ----
    zero_acc();
    gemm512(g_WT3, 0);
    {
        __half* dst = g_Ah + (size_t)(t + 1) * HSLOT;
        #pragma unroll
        for (int mi = 0; mi < 2; ++mi)
            #pragma unroll
            for (int ni = 0; ni < 8; ++ni) {
                float* cc = acc[mi][ni];
                int m = mi * 16 + gid;
                int n = w * 64 + ni * 8 + (tq << 1);
                float b0 = bhv[n], b1 = bhv[n + 1];
                float h0 = tanh_app(cc[0] + __half2float(HGs[m * 512 + n]) + b0);
                float h1 = tanh_app(cc[1] + __half2float(HGs[m * 512 + n + 1]) + b1);
                float h2 = tanh_app(cc[2] + __half2float(HGs[(m + 8) * 512 + n]) + b0);
                float h3 = tanh_app(cc[3] + __half2float(HGs[(m + 8) * 512 + n + 1]) + b1);
                *(__half2*)(dst + (size_t)(m0 + m) * 512 + n) = __floats2half2_rn(h0, h1);
                *(__half2*)(dst + (size_t)(m0 + m + 8) * 512 + n) = __floats2half2_rn(h2, h3);
            }
    }
}

// ---------------- head layers 2,3 ----------------
__global__ void head2_k(const float* __restrict__ HD1, const float* __restrict__ W2,
                        const float* __restrict__ b2, float* __restrict__ HD2) {
    int warp = (blockIdx.x * blockDim.x + threadIdx.x) >> 5;
    int lane = threadIdx.x & 31;
    if (warp >= Bn) return;
    const float* h = HD1 + (size_t)warp * 256;
    float acc = 0.f;
    for (int k = 0; k < 256; ++k) acc = fmaf(h[k], W2[k * 32 + lane], acc);
    HD2[(size_t)warp * 32 + lane] = fmaxf(acc + b2[lane], 0.f);
}

__global__ void head3_k(const float* __restrict__ HD2, const float* __restrict__ W3,
                        const float* __restrict__ b3, float* __restrict__ out) {
    int b = blockIdx.x * blockDim.x + threadIdx.x;
    if (b >= Bn) return;
    float a0 = b3[0], a1 = b3[1];
    const float* h = HD2 + (size_t)b * 32;
    #pragma unroll
    for (int k = 0; k < 32; ++k) {
        float hv = h[k];
        a0 = fmaf(hv, W3[k * 2 + 0], a0);
        a1 = fmaf(hv, W3[k * 2 + 1], a1);
    }
    float m = fmaxf(a0, a1);
    float e0v = expf(a0 - m), e1v = expf(a1 - m);
    float inv = 1.f / (e0v + e1v);
    out[(size_t)b * 2 + 0] = e0v * inv;
    out[(size_t)b * 2 + 1] = e1v * inv;
}

// ---------------- launcher ----------------
extern "C" void kernel_launch(void* const* d_in, const int* in_sizes, int n_in,
                              void* d_out, int out_size) {
    const float* inputs    = (const float*)d_in[0];
    const float* init_proj = (const float*)d_in[1];
    const float* Wx  = (const float*)d_in[3];
    const float* Uh  = (const float*)d_in[4];
    const float* Wt  = (const float*)d_in[5];
    const float* b   = (const float*)d_in[6];
    const float* WxT = (const float*)d_in[7];
    const float* WtT = (const float*)d_in[8];
    const float* bT  = (const float*)d_in[9];
    const float* Wa  = (const float*)d_in[10];
    const float* Wb  = (const float*)d_in[11];
    const float* va  = (const float*)d_in[12];
    const float* ba  = (const float*)d_in[13];
    const float* We  = (const float*)d_in[14];
    const float* Wg  = (const float*)d_in[15];
    const float* bh  = (const float*)d_in[16];
    const float* W1  = (const float*)d_in[17];
    const float* b1  = (const float*)d_in[18];
    const float* W2  = (const float*)d_in[19];
    const float* b2  = (const float*)d_in[20];
    const float* W3  = (const float*)d_in[21];
    const float* b3  = (const float*)d_in[22];
    float* out = (float*)d_out;

    cudaFuncSetAttribute(mma_gemm<1>, cudaFuncAttributeMaxDynamicSharedMemorySize, SMEM_BYTES);
    cudaFuncSetAttribute(mma_gemm<4>, cudaFuncAttributeMaxDynamicSharedMemorySize, SMEM_BYTES);
    cudaFuncSetAttribute(mma_gemm<5>, cudaFuncAttributeMaxDynamicSharedMemorySize, SMEM_BYTES);
    cudaFuncSetAttribute(step_fused, cudaFuncAttributeMaxDynamicSharedMemorySize, FSM_TOTAL);

    __half *Ah, *APRE, *WTb, *WPRE, *WTh, *MEMA16;
    float *HD1, *HD2;
    cudaGetSymbolAddress((void**)&Ah, g_Ah);
    cudaGetSymbolAddress((void**)&APRE, g_APRE);
    cudaGetSymbolAddress((void**)&WTb, g_WTb);
    cudaGetSymbolAddress((void**)&WPRE, g_WPRE);
    cudaGetSymbolAddress((void**)&WTh, g_WTh);
    cudaGetSymbolAddress((void**)&MEMA16, g_MEMA16);
    cudaGetSymbolAddress((void**)&HD1, g_HD1);
    cudaGetSymbolAddress((void**)&HD2, g_HD2);

    prep_weights<<<1024, 256>>>(Uh, Wx, Wt, Wa, WxT, Wb, Wg, We, W1);
    prep_s<<<1, 512>>>(init_proj);
    prep_sA<<<1, 512>>>(Wa);
    prep_A<<<2048, 256>>>(inputs);

    // pre-GEMM: ZX + TG for all steps: [65536 x 64] @ [64 x 2560]
    mma_gemm<5><<<dim3(20, 512), 256, SMEM_BYTES>>>(
        APRE, 64, 64, WPRE,
        /*e0*/ b, /*o0*/ nullptr, /*o2h*/ nullptr,
        /*inp*/ inputs, /*WtT*/ WtT, /*bT*/ bT);

    for (int t = 0; t < 16; ++t) {
        if (t > 0) {
            // h_{t-1} @ [Uh | Wa] -> Z16, MEMA slot t-1
            mma_gemm<1><<<dim3(20, 32), 256, SMEM_BYTES>>>(
                Ah + (size_t)t * HSLOT, 512, 512, WTb,
                /*e0*/ nullptr, /*o0*/ nullptr,
                /*o2h*/ MEMA16 + (size_t)(t - 1) * HSLOT,
                /*inp*/ nullptr, /*WtT*/ nullptr, /*bT*/ nullptr);
        }
        step_fused<<<128, 256, FSM_TOTAL>>>(t, va, ba, bh);
    }

    mma_gemm<4><<<dim3(2, 32), 256, SMEM_BYTES>>>(
        Ah + (size_t)16 * HSLOT, 512, 512, WTh,
        /*e0*/ b1, /*o0*/ HD1, /*o2h*/ nullptr,
        /*inp*/ nullptr, /*WtT*/ nullptr, /*bT*/ nullptr);
    head2_k<<<512, 256>>>(HD1, W2, b2, HD2);
    head3_k<<<16, 256>>>(HD2, W3, b3, out);
}

// round 8
// speedup vs baseline: 1.1124x; 1.1124x over previous
#include <cuda_runtime.h>
#include <cuda_fp16.h>
#include <math.h>
#include <stdint.h>

#define Bn 4096
#define HSLOT ((size_t)Bn * 512)
#define STAGE_BYTES 36864
#define SMEM_BYTES (2 * STAGE_BYTES)

// ---------------- device scratch ----------------
__device__ __half g_Ah[(size_t)17 * HSLOT];         // slot j+1 holds h_j (fp16); slot 0 unused
__device__ __half g_APRE[(size_t)65536 * 64];       // [b*16+t][x(63)|t(1)]
__device__ __half g_WTb[(size_t)2560 * 512];        // [Uh | Wa], n-major
__device__ __half g_WPRE[(size_t)2560 * 64];        // [WxWt-fold | WxT], n-major
__device__ __half g_WT2[1024 * 512];                // [Wb | Wg]
__device__ __half g_WT3[512 * 512];                 // We
__device__ __half g_WTh[256 * 512];                 // W1
__device__ __half g_ZX16[(size_t)16 * Bn * 2048];   // x@Wx + b + t*Wt
__device__ __half g_TG16[(size_t)16 * Bn * 512];    // full Tg gate (precomputed)
__device__ __half g_MEMA16[(size_t)15 * HSLOT];     // slot j: h_j @ Wa
__device__ __half g_Z16[(size_t)Bn * 2048];         // h@Uh for current step
__device__ __half g_HcH[(size_t)Bn * 512];
__device__ __half g_CXH[(size_t)Bn * 512];
__device__ float g_C[(size_t)Bn * 512];
__device__ float g_HB[(size_t)Bn * 512];
__device__ float g_HG[(size_t)Bn * 512];
__device__ float g_HD1[(size_t)Bn * 256];
__device__ float g_HD2[(size_t)Bn * 32];
__device__ float g_s[512];
__device__ float g_sA[512];

__device__ __forceinline__ float sigm(float x) { return 1.f / (1.f + expf(-x)); }

__device__ __forceinline__ uint32_t smem_u32(const void* p) {
    uint32_t a;
    asm("{ .reg .u64 t; cvta.to.shared.u64 t, %1; cvt.u32.u64 %0, t; }" : "=r"(a) : "l"(p));
    return a;
}
__device__ __forceinline__ void ldm4(uint32_t* r, uint32_t a) {
    asm volatile("ldmatrix.sync.aligned.m8n8.x4.shared.b16 {%0,%1,%2,%3}, [%4];"
                 : "=r"(r[0]), "=r"(r[1]), "=r"(r[2]), "=r"(r[3]) : "r"(a));
}
__device__ __forceinline__ void mma16816(float* c, const uint32_t* a, uint32_t b0, uint32_t b1) {
    asm volatile("mma.sync.aligned.m16n8k16.row.col.f32.f16.f16.f32 "
                 "{%0,%1,%2,%3}, {%4,%5,%6,%7}, {%8,%9}, {%0,%1,%2,%3};"
                 : "+f"(c[0]), "+f"(c[1]), "+f"(c[2]), "+f"(c[3])
                 : "r"(a[0]), "r"(a[1]), "r"(a[2]), "r"(a[3]), "r"(b0), "r"(b1));
}
__device__ __forceinline__ void cp16(uint32_t saddr, const void* gptr) {
    asm volatile("cp.async.cg.shared.global [%0], [%1], 16;"
                 :: "r"(saddr), "l"(__cvta_generic_to_global(gptr)) : "memory");
}
__device__ __forceinline__ void cp_commit() {
    asm volatile("cp.async.commit_group;" ::: "memory");
}

// ---------------- prep kernels ----------------
__global__ void prep_weights(const float* __restrict__ Uh, const float* __restrict__ Wx,
                             const float* __restrict__ Wt, const float* __restrict__ Wa,
                             const float* __restrict__ WxT, const float* __restrict__ Wb,
                             const float* __restrict__ Wg, const float* __restrict__ We,
                             const float* __restrict__ W1) {
    int stride = gridDim.x * blockDim.x;
    int t0 = blockIdx.x * blockDim.x + threadIdx.x;
    for (int i = t0; i < 2560 * 512; i += stride) {
        int n = i >> 9, k = i & 511;
        float w = (n < 2048) ? Uh[(size_t)k * 2048 + n] : Wa[(size_t)k * 512 + (n - 2048)];
        g_WTb[i] = __float2half(w);
    }
    for (int i = t0; i < 2560 * 64; i += stride) {
        int n = i >> 6, k = i & 63;
        float w;
        if (k < 63) w = (n < 2048) ? Wx[(size_t)k * 2048 + n] : WxT[(size_t)k * 512 + (n - 2048)];
        else        w = (n < 1536) ? Wt[n] : 0.f;
        g_WPRE[i] = __float2half(w);
    }
    for (int i = t0; i < 1024 * 512; i += stride) {
        int n = i >> 9, k = i & 511;
        float w = (n < 512) ? Wb[(size_t)k * 512 + n] : Wg[(size_t)k * 512 + (n - 512)];
        g_WT2[i] = __float2half(w);
    }
    for (int i = t0; i < 512 * 512; i += stride) {
        int n = i >> 9, k = i & 511;
        g_WT3[i] = __float2half(We[(size_t)k * 512 + n]);
    }
    for (int i = t0; i < 256 * 512; i += stride) {
        int n = i >> 9, k = i & 511;
        g_WTh[i] = __float2half(W1[(size_t)k * 256 + n]);
    }
}

__global__ void prep_s(const float* __restrict__ init_proj) {
    int h = threadIdx.x;
    float s = 0.f;
    for (int f = 0; f < 64; ++f) s += init_proj[f * 512 + h];
    g_s[h] = s;
}

__global__ void prep_sA(const float* __restrict__ Wa) {
    int h = threadIdx.x;
    float acc = 0.f;
    for (int k = 0; k < 512; ++k) acc += g_s[k] * Wa[k * 512 + h];
    g_sA[h] = acc;
}

__global__ void prep_A(const float* __restrict__ inp) {
    int stride = gridDim.x * blockDim.x;
    int t0 = blockIdx.x * blockDim.x + threadIdx.x;
    for (int i = t0; i < 65536 * 64; i += stride) {
        int r = i >> 6, k = i & 63;
        float v = (k < 63) ? inp[(size_t)r * 64 + 1 + k] : inp[(size_t)r * 64];
        g_APRE[i] = __float2half(v);
    }
}

// ---------------- fp16 HMMA GEMM ----------------
// block 128x128, 8 warps of 64x32, k-chunk 64, cp.async double buffer
// MODE 1: N=2560 [Uh|Wa]: c<2048 -> g_Z16 (fp16); else -> o2h (MEMA slot, fp16)
// MODE 2: N=1024 [Wb|Wg]: c<512 -> o0=HB(+e0); else o1=HG (fp32)
// MODE 3: N=512 We: h=tanh(acc + e0[row] + e1) -> oh (next Ah slot, fp16)
// MODE 4: N=256 W1: o0 = relu(acc+e0)
// MODE 5: N=2560 pre: rows r=b*16+t; c<2048 -> ZX16=acc+e0; else TG16=Tg(acc,...)
template <int MODE>
__global__ __launch_bounds__(256, 2)
void mma_gemm(const __half* __restrict__ A, int lda, int K,
              const __half* __restrict__ Bh,
              const float* __restrict__ e0, const float* __restrict__ e1,
              float* __restrict__ o0, float* __restrict__ o1,
              __half* __restrict__ o2h, __half* __restrict__ oh,
              const float* __restrict__ inp, const float* __restrict__ WtT,
              const float* __restrict__ bT) {
    extern __shared__ char smem[];
    uint32_t sb = smem_u32(smem);
    const int tid = threadIdx.x;
    const int lane = tid & 31, wid = tid >> 5;
    const int wm = wid & 1, wn = wid >> 1;
    const int gid = lane >> 2, tq = lane & 3;
    const int m0 = blockIdx.y * 128, n0 = blockIdx.x * 128;

    const int kch = K >> 6;

    float acc[4][4][4];
    #pragma unroll
    for (int a = 0; a < 4; ++a)
        #pragma unroll
        for (int b2 = 0; b2 < 4; ++b2)
            #pragma unroll
            for (int c = 0; c < 4; ++c) acc[a][b2][c] = 0.f;

    auto copy_chunk = [&](int ch, int s) {
        int kc = ch << 6;
        uint32_t base = sb + s * STAGE_BYTES;
        #pragma unroll
        for (int i = 0; i < 4; ++i) {
            int lin = tid + (i << 8);
            int r = lin >> 3;
            int c16 = (lin & 7) << 4;
            cp16(base + r * 144 + c16,
                 (const char*)(A + (size_t)(m0 + r) * lda + kc) + c16);
            cp16(base + 18432 + r * 144 + c16,
                 (const char*)(Bh + (size_t)(n0 + r) * K + kc) + c16);
        }
    };

    copy_chunk(0, 0);
    cp_commit();

    const int arow = wm * 64 + (lane & 15);
    const int acol = (lane >> 4) << 4;
    const int brow = wn * 32 + (lane & 7) + ((lane >> 4) << 3);
    const int bcol = ((lane >> 3) & 1) << 4;

    for (int ch = 0; ch < kch; ++ch) {
        if (ch + 1 < kch) {
            copy_chunk(ch + 1, (ch + 1) & 1);
            cp_commit();
            asm volatile("cp.async.wait_group 1;" ::: "memory");
        } else {
            asm volatile("cp.async.wait_group 0;" ::: "memory");
        }
        __syncthreads();

        uint32_t abase = sb + (ch & 1) * STAGE_BYTES;
        uint32_t bbase = abase + 18432;
        #pragma unroll
        for (int k16 = 0; k16 < 4; ++k16) {
            int kb = k16 << 5;
            uint32_t bf[2][4];
            #pragma unroll
            for (int ni2 = 0; ni2 < 2; ++ni2)
                ldm4(bf[ni2], bbase + (brow + ni2 * 16) * 144 + kb + bcol);
            uint32_t af[4][4];
            #pragma unroll
            for (int mi = 0; mi < 4; ++mi)
                ldm4(af[mi], abase + (arow + mi * 16) * 144 + kb + acol);
            #pragma unroll
            for (int ni2 = 0; ni2 < 2; ++ni2)
                #pragma unroll
                for (int mi = 0; mi < 4; ++mi) {
                    mma16816(acc[mi][ni2 * 2],     af[mi], bf[ni2][0], bf[ni2][1]);
                    mma16816(acc[mi][ni2 * 2 + 1], af[mi], bf[ni2][2], bf[ni2][3]);
                }
        }
        __syncthreads();
    }

    auto epi = [&](int m, int c, float x, float y) {
        if (MODE == 1) {
            if (c < 2048) {
                *(__half2*)(g_Z16 + (size_t)m * 2048 + c) = __floats2half2_rn(x, y);
            } else {
                *(__half2*)(o2h + (size_t)m * 512 + (c - 2048)) = __floats2half2_rn(x, y);
            }
        } else if (MODE == 2) {
            if (c < 512) {
                *(float2*)(o0 + (size_t)m * 512 + c) = make_float2(x + e0[c], y + e0[c + 1]);
            } else {
                *(float2*)(o1 + (size_t)m * 512 + (c - 512)) = make_float2(x, y);
            }
        } else if (MODE == 3) {
            float h0 = tanhf(x + e0[(size_t)m * 512 + c] + e1[c]);
            float h1 = tanhf(y + e0[(size_t)m * 512 + c + 1] + e1[c + 1]);
            *(__half2*)(oh + (size_t)m * 512 + c) = __floats2half2_rn(h0, h1);
        } else if (MODE == 4) {
            *(float2*)(o0 + (size_t)m * 256 + c) =
                make_float2(fmaxf(x + e0[c], 0.f), fmaxf(y + e0[c + 1], 0.f));
        } else {  // MODE 5
            int b_ = m >> 4, t_ = m & 15;
            size_t zr = (size_t)t_ * Bn + b_;
            if (c < 2048) {
                *(__half2*)(g_ZX16 + zr * 2048 + c) =
                    __floats2half2_rn(x + e0[c], y + e0[c + 1]);
            } else {
                int j = c - 2048;
                float tv = inp[(size_t)m * 64];
                float t0v = sigm(x + sigm(tv * WtT[j]) + bT[j]);
                float t1v = sigm(y + sigm(tv * WtT[j + 1]) + bT[j + 1]);
                *(__half2*)(g_TG16 + zr * 512 + j) = __floats2half2_rn(t0v, t1v);
            }
        }
    };

    #pragma unroll
    for (int mi = 0; mi < 4; ++mi) {
        #pragma unroll
        for (int ni = 0; ni < 4; ++ni) {
            float* cc = acc[mi][ni];
            int m = m0 + wm * 64 + mi * 16 + gid;
            int c = n0 + wn * 32 + ni * 8 + (tq << 1);
            epi(m, c, cc[0], cc[1]);
            epi(m + 8, c, cc[2], cc[3]);
        }
    }
}

// ---------------- gates + cell update (fp16 in, fp16 out) ----------------
__global__ void gates_k(const __half* __restrict__ ZX, const __half* __restrict__ Z,
                        const __half* __restrict__ TG,
                        float* __restrict__ C, __half* __restrict__ HcH, int first) {
    int idx = blockIdx.x * blockDim.x + threadIdx.x;
    int b = idx >> 9, j = idx & 511;
    const __half* zx = ZX + (size_t)b * 2048;
    float zi = __half2float(zx[j]);
    float zf = __half2float(zx[j + 512]);
    float zo = __half2float(zx[j + 1024]);
    float zc = __half2float(zx[j + 1536]);
    if (!first) {
        const __half* zh = Z + (size_t)b * 2048;
        zi += __half2float(zh[j]);
        zf += __half2float(zh[j + 512]);
        zo += __half2float(zh[j + 1024]);
        zc += __half2float(zh[j + 1536]);
    }
    float ig = sigm(zi), fg = sigm(zf), og = sigm(zo), ch = tanhf(zc);
    float tg = __half2float(TG[idx]);
    float c = first ? (ig + tg) * ch : fmaf(fg, C[idx], (ig + tg) * ch);
    C[idx] = c;
    HcH[idx] = __float2half(og * tanhf(c));
}

// ---------------- attention over 15-slot memory (fp16 rings, fp32 math) ----------------
__global__ void __launch_bounds__(256) attn_k(const float* __restrict__ HB,
                                              const float* __restrict__ va,
                                              __half* __restrict__ CXH, int t) {
    int b = blockIdx.x, tid = threadIdx.x;
    __shared__ float sred[15][8];
    __shared__ float se[15];
    float hb0 = HB[(size_t)b * 512 + tid], hb1 = HB[(size_t)b * 512 + tid + 256];
    float va0 = va[tid], va1 = va[tid + 256];
    int lane = tid & 31, wp = tid >> 5;

    #pragma unroll
    for (int d = 0; d < 15; ++d) {
        int j = t - 15 + d;
        float ma0, ma1;
        if (j < 0) {
            ma0 = g_sA[tid]; ma1 = g_sA[tid + 256];
        } else {
            const __half* ma = g_MEMA16 + (size_t)j * HSLOT + (size_t)b * 512;
            ma0 = __half2float(ma[tid]); ma1 = __half2float(ma[tid + 256]);
        }
        float s = va0 * tanhf(ma0 + hb0) + va1 * tanhf(ma1 + hb1);
        #pragma unroll
        for (int off = 16; off; off >>= 1) s += __shfl_xor_sync(0xffffffffu, s, off);
        if (lane == 0) sred[d][wp] = s;
    }
    __syncthreads();
    if (tid < 15) {
        float e = 0.f;
        #pragma unroll
        for (int w2 = 0; w2 < 8; ++w2) e += sred[tid][w2];
        se[tid] = e;
    }
    __syncthreads();

    float mx = -1e30f;
    #pragma unroll
    for (int d = 0; d < 15; ++d) mx = fmaxf(mx, se[d]);
    float al[15], sum = 0.f;
    #pragma unroll
    for (int d = 0; d < 15; ++d) { al[d] = expf(se[d] - mx); sum += al[d]; }
    float inv = 1.f / sum;
    float c0 = 0.f, c1 = 0.f;
    #pragma unroll
    for (int d = 0; d < 15; ++d) {
        int j = t - 15 + d;
        float a = al[d] * inv;
        float m0, m1;
        if (j < 0) {
            m0 = g_s[tid]; m1 = g_s[tid + 256];
        } else {
            const __half* mm = g_Ah + (size_t)(j + 1) * HSLOT + (size_t)b * 512;
            m0 = __half2float(mm[tid]); m1 = __half2float(mm[tid + 256]);
        }
        c0 = fmaf(a, m0, c0);
        c1 = fmaf(a, m1, c1);
    }
    CXH[(size_t)b * 512 + tid] = __float2half(c0);
    CXH[(size_t)b * 512 + tid + 256] = __float2half(c1);
}

// ---------------- head layers 2,3 ----------------
__global__ void head2_k(const float* __restrict__ HD1, const float* __restrict__ W2,
                        const float* __restrict__ b2, float* __restrict__ HD2) {
    int warp = (blockIdx.x * blockDim.x + threadIdx.x) >> 5;
    int lane = threadIdx.x & 31;
    if (warp >= Bn) return;
    const float* h = HD1 + (size_t)warp * 256;
    float acc = 0.f;
    for (int k = 0; k < 256; ++k) acc = fmaf(h[k], W2[k * 32 + lane], acc);
    HD2[(size_t)warp * 32 + lane] = fmaxf(acc + b2[lane], 0.f);
}

__global__ void head3_k(const float* __restrict__ HD2, const float* __restrict__ W3,
                        const float* __restrict__ b3, float* __restrict__ out) {
    int b = blockIdx.x * blockDim.x + threadIdx.x;
    if (b >= Bn) return;
    float a0 = b3[0], a1 = b3[1];
    const float* h = HD2 + (size_t)b * 32;
    #pragma unroll
    for (int k = 0; k < 32; ++k) {
        float hv = h[k];
        a0 = fmaf(hv, W3[k * 2 + 0], a0);
        a1 = fmaf(hv, W3[k * 2 + 1], a1);
    }
    float m = fmaxf(a0, a1);
    float e0v = expf(a0 - m), e1v = expf(a1 - m);
    float inv = 1.f / (e0v + e1v);
    out[(size_t)b * 2 + 0] = e0v * inv;
    out[(size_t)b * 2 + 1] = e1v * inv;
}

// ---------------- launcher ----------------
extern "C" void kernel_launch(void* const* d_in, const int* in_sizes, int n_in,
                              void* d_out, int out_size) {
    const float* inputs    = (const float*)d_in[0];
    const float* init_proj = (const float*)d_in[1];
    const float* Wx  = (const float*)d_in[3];
    const float* Uh  = (const float*)d_in[4];
    const float* Wt  = (const float*)d_in[5];
    const float* b   = (const float*)d_in[6];
    const float* WxT = (const float*)d_in[7];
    const float* WtT = (const float*)d_in[8];
    const float* bT  = (const float*)d_in[9];
    const float* Wa  = (const float*)d_in[10];
    const float* Wb  = (const float*)d_in[11];
    const float* va  = (const float*)d_in[12];
    const float* ba  = (const float*)d_in[13];
    const float* We  = (const float*)d_in[14];
    const float* Wg  = (const float*)d_in[15];
    const float* bh  = (const float*)d_in[16];
    const float* W1  = (const float*)d_in[17];
    const float* b1  = (const float*)d_in[18];
    const float* W2  = (const float*)d_in[19];
    const float* b2  = (const float*)d_in[20];
    const float* W3  = (const float*)d_in[21];
    const float* b3  = (const float*)d_in[22];
    float* out = (float*)d_out;

    cudaFuncSetAttribute(mma_gemm<1>, cudaFuncAttributeMaxDynamicSharedMemorySize, SMEM_BYTES);
    cudaFuncSetAttribute(mma_gemm<2>, cudaFuncAttributeMaxDynamicSharedMemorySize, SMEM_BYTES);
    cudaFuncSetAttribute(mma_gemm<3>, cudaFuncAttributeMaxDynamicSharedMemorySize, SMEM_BYTES);
    cudaFuncSetAttribute(mma_gemm<4>, cudaFuncAttributeMaxDynamicSharedMemorySize, SMEM_BYTES);
    cudaFuncSetAttribute(mma_gemm<5>, cudaFuncAttributeMaxDynamicSharedMemorySize, SMEM_BYTES);

    __half *Ah, *APRE, *WTb, *WPRE, *WT2, *WT3, *WTh, *MEMA16, *Z16, *ZX16, *TG16, *HcH, *CXH;
    float *C, *HB, *HG, *HD1, *HD2;
    cudaGetSymbolAddress((void**)&Ah, g_Ah);
    cudaGetSymbolAddress((void**)&APRE, g_APRE);
    cudaGetSymbolAddress((void**)&WTb, g_WTb);
    cudaGetSymbolAddress((void**)&WPRE, g_WPRE);
    cudaGetSymbolAddress((void**)&WT2, g_WT2);
    cudaGetSymbolAddress((void**)&WT3, g_WT3);
    cudaGetSymbolAddress((void**)&WTh, g_WTh);
    cudaGetSymbolAddress((void**)&MEMA16, g_MEMA16);
    cudaGetSymbolAddress((void**)&Z16, g_Z16);
    cudaGetSymbolAddress((void**)&ZX16, g_ZX16);
    cudaGetSymbolAddress((void**)&TG16, g_TG16);
    cudaGetSymbolAddress((void**)&HcH, g_HcH);
    cudaGetSymbolAddress((void**)&CXH, g_CXH);
    cudaGetSymbolAddress((void**)&C, g_C);
    cudaGetSymbolAddress((void**)&HB, g_HB);
    cudaGetSymbolAddress((void**)&HG, g_HG);
    cudaGetSymbolAddress((void**)&HD1, g_HD1);
    cudaGetSymbolAddress((void**)&HD2, g_HD2);

    prep_weights<<<1024, 256>>>(Uh, Wx, Wt, Wa, WxT, Wb, Wg, We, W1);
    prep_s<<<1, 512>>>(init_proj);
    prep_sA<<<1, 512>>>(Wa);
    prep_A<<<2048, 256>>>(inputs);

    // pre-GEMM: ZX + TG for all steps: [65536 x 64] @ [64 x 2560]
    mma_gemm<5><<<dim3(20, 512), 256, SMEM_BYTES>>>(
        APRE, 64, 64, WPRE,
        /*e0*/ b, /*e1*/ nullptr, /*o0*/ nullptr, /*o1*/ nullptr,
        /*o2h*/ nullptr, /*oh*/ nullptr,
        /*inp*/ inputs, /*WtT*/ WtT, /*bT*/ bT);

    for (int t = 0; t < 16; ++t) {
        if (t > 0) {
            mma_gemm<1><<<dim3(20, 32), 256, SMEM_BYTES>>>(
                Ah + (size_t)t * HSLOT, 512, 512, WTb,
                /*e0*/ nullptr, /*e1*/ nullptr, /*o0*/ nullptr, /*o1*/ nullptr,
                /*o2h*/ MEMA16 + (size_t)(t - 1) * HSLOT, /*oh*/ nullptr,
                /*inp*/ nullptr, /*WtT*/ nullptr, /*bT*/ nullptr);
        }
        gates_k<<<8192, 256>>>(ZX16 + (size_t)t * Bn * 2048, Z16,
                               TG16 + (size_t)t * Bn * 512, C, HcH, t == 0);
        mma_gemm<2><<<dim3(8, 32), 256, SMEM_BYTES>>>(
            HcH, 512, 512, WT2,
            /*e0*/ ba, /*e1*/ nullptr, /*o0*/ HB, /*o1*/ HG,
            /*o2h*/ nullptr, /*oh*/ nullptr,
            /*inp*/ nullptr, /*WtT*/ nullptr, /*bT*/ nullptr);
        attn_k<<<4096, 256>>>(HB, va, CXH, t);
        mma_gemm<3><<<dim3(4, 32), 256, SMEM_BYTES>>>(
            CXH, 512, 512, WT3,
            /*e0*/ HG, /*e1*/ bh, /*o0*/ nullptr, /*o1*/ nullptr,
            /*o2h*/ nullptr, /*oh*/ Ah + (size_t)(t + 1) * HSLOT,
            /*inp*/ nullptr, /*WtT*/ nullptr, /*bT*/ nullptr);
    }

    mma_gemm<4><<<dim3(2, 32), 256, SMEM_BYTES>>>(
        Ah + (size_t)16 * HSLOT, 512, 512, WTh,
        /*e0*/ b1, /*e1*/ nullptr, /*o0*/ HD1, /*o1*/ nullptr,
        /*o2h*/ nullptr, /*oh*/ nullptr,
        /*inp*/ nullptr, /*WtT*/ nullptr, /*bT*/ nullptr);
    head2_k<<<512, 256>>>(HD1, W2, b2, HD2);
    head3_k<<<16, 256>>>(HD2, W3, b3, out);
}

// round 9
// speedup vs baseline: 1.1959x; 1.0751x over previous
#include <cuda_runtime.h>
#include <cuda_fp16.h>
#include <math.h>
#include <stdint.h>

#define Bn 4096
#define HSLOT ((size_t)Bn * 512)
#define STAGE_BYTES 36864
#define SMEM_BYTES (2 * STAGE_BYTES)

// Gate permutation: physical col p (p<2048) <-> logical (gate g, unit j):
//   g = (p>>3)&3, j = ((p>>5)<<3) + (p&7)
// so each 32-col block = [i(8) f(8) o(8) c(8)] of 8 consecutive units.

// ---------------- device scratch ----------------
__device__ __half g_Ah[(size_t)17 * HSLOT];         // slot j+1 holds h_j (fp16); slot 0 unused
__device__ __half g_APRE[(size_t)65536 * 64];       // [b*16+t][x(63)|t(1)]
__device__ __half g_WTb[(size_t)2560 * 512];        // [Uh(perm) | Wa], n-major
__device__ __half g_WPRE[(size_t)2560 * 64];        // [WxWt(perm) | WxT], n-major
__device__ __half g_WT2[1024 * 512];                // [Wb | Wg]
__device__ __half g_WT3[512 * 512];                 // We
__device__ __half g_WTh[256 * 512];                 // W1
__device__ __half g_ZX16[(size_t)16 * Bn * 2048];   // x@Wx + b + t*Wt (gate-permuted cols)
__device__ __half g_TG16[(size_t)16 * Bn * 512];    // full Tg gate (precomputed)
__device__ __half g_MEMA16[(size_t)15 * HSLOT];     // slot j: h_j @ Wa
__device__ __half g_HcH[(size_t)Bn * 512];
__device__ __half g_HBh[(size_t)Bn * 512];
__device__ __half g_CXH[(size_t)Bn * 512];
__device__ float g_C[(size_t)Bn * 512];
__device__ float g_HG[(size_t)Bn * 512];
__device__ float g_HD1[(size_t)Bn * 256];
__device__ float g_HD2[(size_t)Bn * 32];
__device__ float g_s[512];
__device__ float g_sA[512];

__device__ __forceinline__ float sigm(float x) { return 1.f / (1.f + expf(-x)); }
__device__ __forceinline__ float sigmf_(float x) { return __fdividef(1.f, 1.f + __expf(-x)); }
__device__ __forceinline__ float tanh_app(float x) {
    float y; asm("tanh.approx.f32 %0, %1;" : "=f"(y) : "f"(x)); return y;
}

__device__ __forceinline__ uint32_t smem_u32(const void* p) {
    uint32_t a;
    asm("{ .reg .u64 t; cvta.to.shared.u64 t, %1; cvt.u32.u64 %0, t; }" : "=r"(a) : "l"(p));
    return a;
}
__device__ __forceinline__ void ldm4(uint32_t* r, uint32_t a) {
    asm volatile("ldmatrix.sync.aligned.m8n8.x4.shared.b16 {%0,%1,%2,%3}, [%4];"
                 : "=r"(r[0]), "=r"(r[1]), "=r"(r[2]), "=r"(r[3]) : "r"(a));
}
__device__ __forceinline__ void mma16816(float* c, const uint32_t* a, uint32_t b0, uint32_t b1) {
    asm volatile("mma.sync.aligned.m16n8k16.row.col.f32.f16.f16.f32 "
                 "{%0,%1,%2,%3}, {%4,%5,%6,%7}, {%8,%9}, {%0,%1,%2,%3};"
                 : "+f"(c[0]), "+f"(c[1]), "+f"(c[2]), "+f"(c[3])
                 : "r"(a[0]), "r"(a[1]), "r"(a[2]), "r"(a[3]), "r"(b0), "r"(b1));
}
__device__ __forceinline__ void cp16(uint32_t saddr, const void* gptr) {
    asm volatile("cp.async.cg.shared.global [%0], [%1], 16;"
                 :: "r"(saddr), "l"(__cvta_generic_to_global(gptr)) : "memory");
}
__device__ __forceinline__ void cp_commit() {
    asm volatile("cp.async.commit_group;" ::: "memory");
}

// ---------------- prep kernels ----------------
__global__ void prep_weights(const float* __restrict__ Uh, const float* __restrict__ Wx,
                             const float* __restrict__ Wt, const float* __restrict__ Wa,
                             const float* __restrict__ WxT, const float* __restrict__ Wb,
                             const float* __restrict__ Wg, const float* __restrict__ We,
                             const float* __restrict__ W1) {
    int stride = gridDim.x * blockDim.x;
    int t0 = blockIdx.x * blockDim.x + threadIdx.x;
    for (int i = t0; i < 2560 * 512; i += stride) {
        int n = i >> 9, k = i & 511;
        float w;
        if (n < 2048) {
            int g = (n >> 3) & 3, j = ((n >> 5) << 3) + (n & 7);
            w = Uh[(size_t)k * 2048 + g * 512 + j];
        } else {
            w = Wa[(size_t)k * 512 + (n - 2048)];
        }
        g_WTb[i] = __float2half(w);
    }
    for (int i = t0; i < 2560 * 64; i += stride) {
        int n = i >> 6, k = i & 63;
        float w;
        if (n < 2048) {
            int g = (n >> 3) & 3, j = ((n >> 5) << 3) + (n & 7);
            if (k < 63) w = Wx[(size_t)k * 2048 + g * 512 + j];
            else        w = (g < 3) ? Wt[g * 512 + j] : 0.f;
        } else {
            w = (k < 63) ? WxT[(size_t)k * 512 + (n - 2048)] : 0.f;
        }
        g_WPRE[i] = __float2half(w);
    }
    for (int i = t0; i < 1024 * 512; i += stride) {
        int n = i >> 9, k = i & 511;
        float w = (n < 512) ? Wb[(size_t)k * 512 + n] : Wg[(size_t)k * 512 + (n - 512)];
        g_WT2[i] = __float2half(w);
    }
    for (int i = t0; i < 512 * 512; i += stride) {
        int n = i >> 9, k = i & 511;
        g_WT3[i] = __float2half(We[(size_t)k * 512 + n]);
    }
    for (int i = t0; i < 256 * 512; i += stride) {
        int n = i >> 9, k = i & 511;
        g_WTh[i] = __float2half(W1[(size_t)k * 256 + n]);
    }
}

__global__ void prep_s(const float* __restrict__ init_proj) {
    int h = threadIdx.x;
    float s = 0.f;
    for (int f = 0; f < 64; ++f) s += init_proj[f * 512 + h];
    g_s[h] = s;
}

__global__ void prep_sA(const float* __restrict__ Wa) {
    int h = threadIdx.x;
    float acc = 0.f;
    for (int k = 0; k < 512; ++k) acc += g_s[k] * Wa[k * 512 + h];
    g_sA[h] = acc;
}

__global__ void prep_A(const float* __restrict__ inp) {
    int stride = gridDim.x * blockDim.x;
    int t0 = blockIdx.x * blockDim.x + threadIdx.x;
    for (int i = t0; i < 65536 * 64; i += stride) {
        int r = i >> 6, k = i & 63;
        float v = (k < 63) ? inp[(size_t)r * 64 + 1 + k] : inp[(size_t)r * 64];
        g_APRE[i] = __float2half(v);
    }
}

// ---------------- fp16 HMMA GEMM ----------------
// block 128x128, 8 warps of 64x32, k-chunk 64, cp.async double buffer
// MODE 1: N=2560 [Uh(perm)|Wa]: c<2048 -> FUSED gates/cell update -> C, HcH(oh); else MEMA(o2h)
// MODE 2: N=1024 [Wb|Wg]: c<512 -> o2h=HBh(+e0, fp16); else o1=HG (fp32)
// MODE 3: N=512 We: h=tanh(acc + e0[row] + e1) -> oh (next Ah slot, fp16)
// MODE 4: N=256 W1: o0 = relu(acc+e0)
// MODE 5: N=2560 pre: rows r=b*16+t; c<2048 -> ZX16=acc+b[logical] (perm); else TG16
template <int MODE>
__global__ __launch_bounds__(256, 2)
void mma_gemm(const __half* __restrict__ A, int lda, int K,
              const __half* __restrict__ Bh,
              const float* __restrict__ e0, const float* __restrict__ e1,
              float* __restrict__ o0, float* __restrict__ o1,
              __half* __restrict__ o2h, __half* __restrict__ oh,
              const __half* __restrict__ zxp, const __half* __restrict__ tgp,
              float* __restrict__ Cp,
              const float* __restrict__ inp, const float* __restrict__ WtT,
              const float* __restrict__ bT) {
    extern __shared__ char smem[];
    uint32_t sb = smem_u32(smem);
    const int tid = threadIdx.x;
    const int lane = tid & 31, wid = tid >> 5;
    const int wm = wid & 1, wn = wid >> 1;
    const int gid = lane >> 2, tq = lane & 3;
    const int m0 = blockIdx.y * 128, n0 = blockIdx.x * 128;

    const int kch = K >> 6;

    float acc[4][4][4];
    #pragma unroll
    for (int a = 0; a < 4; ++a)
        #pragma unroll
        for (int b2 = 0; b2 < 4; ++b2)
            #pragma unroll
            for (int c = 0; c < 4; ++c) acc[a][b2][c] = 0.f;

    auto copy_chunk = [&](int ch, int s) {
        int kc = ch << 6;
        uint32_t base = sb + s * STAGE_BYTES;
        #pragma unroll
        for (int i = 0; i < 4; ++i) {
            int lin = tid + (i << 8);
            int r = lin >> 3;
            int c16 = (lin & 7) << 4;
            cp16(base + r * 144 + c16,
                 (const char*)(A + (size_t)(m0 + r) * lda + kc) + c16);
            cp16(base + 18432 + r * 144 + c16,
                 (const char*)(Bh + (size_t)(n0 + r) * K + kc) + c16);
        }
    };

    copy_chunk(0, 0);
    cp_commit();

    const int arow = wm * 64 + (lane & 15);
    const int acol = (lane >> 4) << 4;
    const int brow = wn * 32 + (lane & 7) + ((lane >> 4) << 3);
    const int bcol = ((lane >> 3) & 1) << 4;

    for (int ch = 0; ch < kch; ++ch) {
        if (ch + 1 < kch) {
            copy_chunk(ch + 1, (ch + 1) & 1);
            cp_commit();
            asm volatile("cp.async.wait_group 1;" ::: "memory");
        } else {
            asm volatile("cp.async.wait_group 0;" ::: "memory");
        }
        __syncthreads();

        uint32_t abase = sb + (ch & 1) * STAGE_BYTES;
        uint32_t bbase = abase + 18432;
        #pragma unroll
        for (int k16 = 0; k16 < 4; ++k16) {
            int kb = k16 << 5;
            uint32_t bf[2][4];
            #pragma unroll
            for (int ni2 = 0; ni2 < 2; ++ni2)
                ldm4(bf[ni2], bbase + (brow + ni2 * 16) * 144 + kb + bcol);
            uint32_t af[4][4];
            #pragma unroll
            for (int mi = 0; mi < 4; ++mi)
                ldm4(af[mi], abase + (arow + mi * 16) * 144 + kb + acol);
            #pragma unroll
            for (int ni2 = 0; ni2 < 2; ++ni2)
                #pragma unroll
                for (int mi = 0; mi < 4; ++mi) {
                    mma16816(acc[mi][ni2 * 2],     af[mi], bf[ni2][0], bf[ni2][1]);
                    mma16816(acc[mi][ni2 * 2 + 1], af[mi], bf[ni2][2], bf[ni2][3]);
                }
        }
        __syncthreads();
    }

    // ---- epilogues ----
    if (MODE == 1) {
        if (n0 < 2048) {
            // fused LSTM gates: ni == gate index (i,f,o,c) thanks to column permutation
            int blk = (n0 + wn * 32) >> 5;
            int j = blk * 8 + (tq << 1);
            #pragma unroll
            for (int mi = 0; mi < 4; ++mi) {
                int mb = m0 + wm * 64 + mi * 16 + gid;
                #pragma unroll
                for (int hf = 0; hf < 2; ++hf) {
                    int r = mb + hf * 8;
                    int ko = hf * 2;
                    const __half* zxr = zxp + (size_t)r * 2048 + blk * 32 + (tq << 1);
                    float2 xi = __half22float2(*(const __half2*)(zxr));
                    float2 xf = __half22float2(*(const __half2*)(zxr + 8));
                    float2 xo = __half22float2(*(const __half2*)(zxr + 16));
                    float2 xc = __half22float2(*(const __half2*)(zxr + 24));
                    float2 tg2 = __half22float2(*(const __half2*)(tgp + (size_t)r * 512 + j));
                    float2 cold = *(float2*)(Cp + (size_t)r * 512 + j);
                    float ch0 = tanh_app(acc[mi][3][ko] + xc.x);
                    float ch1 = tanh_app(acc[mi][3][ko + 1] + xc.y);
                    float c0 = fmaf(sigmf_(acc[mi][1][ko] + xf.x), cold.x,
                                    (sigmf_(acc[mi][0][ko] + xi.x) + tg2.x) * ch0);
                    float c1 = fmaf(sigmf_(acc[mi][1][ko + 1] + xf.y), cold.y,
                                    (sigmf_(acc[mi][0][ko + 1] + xi.y) + tg2.y) * ch1);
                    *(float2*)(Cp + (size_t)r * 512 + j) = make_float2(c0, c1);
                    float h0 = sigmf_(acc[mi][2][ko] + xo.x) * tanh_app(c0);
                    float h1 = sigmf_(acc[mi][2][ko + 1] + xo.y) * tanh_app(c1);
                    *(__half2*)(oh + (size_t)r * 512 + j) = __floats2half2_rn(h0, h1);
                }
            }
        } else {
            #pragma unroll
            for (int mi = 0; mi < 4; ++mi)
                #pragma unroll
                for (int ni = 0; ni < 4; ++ni) {
                    float* cc = acc[mi][ni];
                    int m = m0 + wm * 64 + mi * 16 + gid;
                    int c = n0 + wn * 32 + ni * 8 + (tq << 1) - 2048;
                    *(__half2*)(o2h + (size_t)m * 512 + c) = __floats2half2_rn(cc[0], cc[1]);
                    *(__half2*)(o2h + (size_t)(m + 8) * 512 + c) = __floats2half2_rn(cc[2], cc[3]);
                }
        }
        return;
    }

    auto epi = [&](int m, int c, float x, float y) {
        if (MODE == 2) {
            if (c < 512) {
                *(__half2*)(o2h + (size_t)m * 512 + c) =
                    __floats2half2_rn(x + e0[c], y + e0[c + 1]);
            } else {
                *(float2*)(o1 + (size_t)m * 512 + (c - 512)) = make_float2(x, y);
            }
        } else if (MODE == 3) {
            float h0 = tanh_app(x + e0[(size_t)m * 512 + c] + e1[c]);
            float h1 = tanh_app(y + e0[(size_t)m * 512 + c + 1] + e1[c + 1]);
            *(__half2*)(oh + (size_t)m * 512 + c) = __floats2half2_rn(h0, h1);
        } else if (MODE == 4) {
            *(float2*)(o0 + (size_t)m * 256 + c) =
                make_float2(fmaxf(x + e0[c], 0.f), fmaxf(y + e0[c + 1], 0.f));
        } else {  // MODE 5
            int b_ = m >> 4, t_ = m & 15;
            size_t zr = (size_t)t_ * Bn + b_;
            if (c < 2048) {
                int g = (c >> 3) & 3;
                int j0 = ((c >> 5) << 3) + (c & 7);
                *(__half2*)(g_ZX16 + zr * 2048 + c) =
                    __floats2half2_rn(x + e0[g * 512 + j0], y + e0[g * 512 + j0 + 1]);
            } else {
                int j = c - 2048;
                float tv = inp[(size_t)m * 64];
                float t0v = sigm(x + sigm(tv * WtT[j]) + bT[j]);
                float t1v = sigm(y + sigm(tv * WtT[j + 1]) + bT[j + 1]);
                *(__half2*)(g_TG16 + zr * 512 + j) = __floats2half2_rn(t0v, t1v);
            }
        }
    };

    #pragma unroll
    for (int mi = 0; mi < 4; ++mi) {
        #pragma unroll
        for (int ni = 0; ni < 4; ++ni) {
            float* cc = acc[mi][ni];
            int m = m0 + wm * 64 + mi * 16 + gid;
            int c = n0 + wn * 32 + ni * 8 + (tq << 1);
            epi(m, c, cc[0], cc[1]);
            epi(m + 8, c, cc[2], cc[3]);
        }
    }
}

// ---------------- t=0 gates (no h contribution; reads permuted ZX) ----------------
__global__ void gates0_k(const __half* __restrict__ ZX, const __half* __restrict__ TG,
                         float* __restrict__ C, __half* __restrict__ HcH) {
    int idx = blockIdx.x * blockDim.x + threadIdx.x;
    int b = idx >> 9, j = idx & 511;
    int blk = j >> 3, jr = j & 7;
    const __half* zx = ZX + (size_t)b * 2048 + blk * 32 + jr;
    float zi = __half2float(zx[0]);
    float zf = __half2float(zx[8]);   (void)zf;
    float zo = __half2float(zx[16]);
    float zc = __half2float(zx[24]);
    float tg = __half2float(TG[idx]);
    float ch = tanh_app(zc);
    float c = (sigmf_(zi) + tg) * ch;
    C[idx] = c;
    HcH[idx] = __float2half(sigmf_(zo) * tanh_app(c));
}

// ---------------- attention over 15-slot memory (fp16 rings, fast math) ----------------
__global__ void __launch_bounds__(256) attn_k(const __half* __restrict__ HB,
                                              const float* __restrict__ va,
                                              __half* __restrict__ CXH, int t) {
    int b = blockIdx.x, tid = threadIdx.x;
    __shared__ float sred[15][8];
    __shared__ float se[15];
    float hb0 = __half2float(HB[(size_t)b * 512 + tid]);
    float hb1 = __half2float(HB[(size_t)b * 512 + tid + 256]);
    float va0 = va[tid], va1 = va[tid + 256];
    int lane = tid & 31, wp = tid >> 5;

    #pragma unroll
    for (int d = 0; d < 15; ++d) {
        int j = t - 15 + d;
        float ma0, ma1;
        if (j < 0) {
            ma0 = g_sA[tid]; ma1 = g_sA[tid + 256];
        } else {
            const __half* ma = g_MEMA16 + (size_t)j * HSLOT + (size_t)b * 512;
            ma0 = __half2float(ma[tid]); ma1 = __half2float(ma[tid + 256]);
        }
        float s = va0 * tanh_app(ma0 + hb0) + va1 * tanh_app(ma1 + hb1);
        #pragma unroll
        for (int off = 16; off; off >>= 1) s += __shfl_xor_sync(0xffffffffu, s, off);
        if (lane == 0) sred[d][wp] = s;
    }
    __syncthreads();
    if (tid < 15) {
        float e = 0.f;
        #pragma unroll
        for (int w2 = 0; w2 < 8; ++w2) e += sred[tid][w2];
        se[tid] = e;
    }
    __syncthreads();

    float mx = -1e30f;
    #pragma unroll
    for (int d = 0; d < 15; ++d) mx = fmaxf(mx, se[d]);
    float al[15], sum = 0.f;
    #pragma unroll
    for (int d = 0; d < 15; ++d) { al[d] = __expf(se[d] - mx); sum += al[d]; }
    float inv = __fdividef(1.f, sum);
    float c0 = 0.f, c1 = 0.f;
    #pragma unroll
    for (int d = 0; d < 15; ++d) {
        int j = t - 15 + d;
        float a = al[d] * inv;
        float m0, m1;
        if (j < 0) {
            m0 = g_s[tid]; m1 = g_s[tid + 256];
        } else {
            const __half* mm = g_Ah + (size_t)(j + 1) * HSLOT + (size_t)b * 512;
            m0 = __half2float(mm[tid]); m1 = __half2float(mm[tid + 256]);
        }
        c0 = fmaf(a, m0, c0);
        c1 = fmaf(a, m1, c1);
    }
    CXH[(size_t)b * 512 + tid] = __float2half(c0);
    CXH[(size_t)b * 512 + tid + 256] = __float2half(c1);
}

// ---------------- head layers 2,3 ----------------
__global__ void head2_k(const float* __restrict__ HD1, const float* __restrict__ W2,
                        const float* __restrict__ b2, float* __restrict__ HD2) {
    int warp = (blockIdx.x * blockDim.x + threadIdx.x) >> 5;
    int lane = threadIdx.x & 31;
    if (warp >= Bn) return;
    const float* h = HD1 + (size_t)warp * 256;
    float acc = 0.f;
    for (int k = 0; k < 256; ++k) acc = fmaf(h[k], W2[k * 32 + lane], acc);
    HD2[(size_t)warp * 32 + lane] = fmaxf(acc + b2[lane], 0.f);
}

__global__ void head3_k(const float* __restrict__ HD2, const float* __restrict__ W3,
                        const float* __restrict__ b3, float* __restrict__ out) {
    int b = blockIdx.x * blockDim.x + threadIdx.x;
    if (b >= Bn) return;
    float a0 = b3[0], a1 = b3[1];
    const float* h = HD2 + (size_t)b * 32;
    #pragma unroll
    for (int k = 0; k < 32; ++k) {
        float hv = h[k];
        a0 = fmaf(hv, W3[k * 2 + 0], a0);
        a1 = fmaf(hv, W3[k * 2 + 1], a1);
    }
    float m = fmaxf(a0, a1);
    float e0v = expf(a0 - m), e1v = expf(a1 - m);
    float inv = 1.f / (e0v + e1v);
    out[(size_t)b * 2 + 0] = e0v * inv;
    out[(size_t)b * 2 + 1] = e1v * inv;
}

// ---------------- launcher ----------------
extern "C" void kernel_launch(void* const* d_in, const int* in_sizes, int n_in,
                              void* d_out, int out_size) {
    const float* inputs    = (const float*)d_in[0];
    const float* init_proj = (const float*)d_in[1];
    const float* Wx  = (const float*)d_in[3];
    const float* Uh  = (const float*)d_in[4];
    const float* Wt  = (const float*)d_in[5];
    const float* b   = (const float*)d_in[6];
    const float* WxT = (const float*)d_in[7];
    const float* WtT = (const float*)d_in[8];
    const float* bT  = (const float*)d_in[9];
    const float* Wa  = (const float*)d_in[10];
    const float* Wb  = (const float*)d_in[11];
    const float* va  = (const float*)d_in[12];
    const float* ba  = (const float*)d_in[13];
    const float* We  = (const float*)d_in[14];
    const float* Wg  = (const float*)d_in[15];
    const float* bh  = (const float*)d_in[16];
    const float* W1  = (const float*)d_in[17];
    const float* b1  = (const float*)d_in[18];
    const float* W2  = (const float*)d_in[19];
    const float* b2  = (const float*)d_in[20];
    const float* W3  = (const float*)d_in[21];
    const float* b3  = (const float*)d_in[22];
    float* out = (float*)d_out;

    cudaFuncSetAttribute(mma_gemm<1>, cudaFuncAttributeMaxDynamicSharedMemorySize, SMEM_BYTES);
    cudaFuncSetAttribute(mma_gemm<2>, cudaFuncAttributeMaxDynamicSharedMemorySize, SMEM_BYTES);
    cudaFuncSetAttribute(mma_gemm<3>, cudaFuncAttributeMaxDynamicSharedMemorySize, SMEM_BYTES);
    cudaFuncSetAttribute(mma_gemm<4>, cudaFuncAttributeMaxDynamicSharedMemorySize, SMEM_BYTES);
    cudaFuncSetAttribute(mma_gemm<5>, cudaFuncAttributeMaxDynamicSharedMemorySize, SMEM_BYTES);

    __half *Ah, *APRE, *WTb, *WPRE, *WT2, *WT3, *WTh, *MEMA16, *ZX16, *TG16, *HcH, *HBh, *CXH;
    float *C, *HG, *HD1, *HD2;
    cudaGetSymbolAddress((void**)&Ah, g_Ah);
    cudaGetSymbolAddress((void**)&APRE, g_APRE);
    cudaGetSymbolAddress((void**)&WTb, g_WTb);
    cudaGetSymbolAddress((void**)&WPRE, g_WPRE);
    cudaGetSymbolAddress((void**)&WT2, g_WT2);
    cudaGetSymbolAddress((void**)&WT3, g_WT3);
    cudaGetSymbolAddress((void**)&WTh, g_WTh);
    cudaGetSymbolAddress((void**)&MEMA16, g_MEMA16);
    cudaGetSymbolAddress((void**)&ZX16, g_ZX16);
    cudaGetSymbolAddress((void**)&TG16, g_TG16);
    cudaGetSymbolAddress((void**)&HcH, g_HcH);
    cudaGetSymbolAddress((void**)&HBh, g_HBh);
    cudaGetSymbolAddress((void**)&CXH, g_CXH);
    cudaGetSymbolAddress((void**)&C, g_C);
    cudaGetSymbolAddress((void**)&HG, g_HG);
    cudaGetSymbolAddress((void**)&HD1, g_HD1);
    cudaGetSymbolAddress((void**)&HD2, g_HD2);

    prep_weights<<<1024, 256>>>(Uh, Wx, Wt, Wa, WxT, Wb, Wg, We, W1);
    prep_s<<<1, 512>>>(init_proj);
    prep_sA<<<1, 512>>>(Wa);
    prep_A<<<2048, 256>>>(inputs);

    // pre-GEMM: ZX(perm) + TG for all steps: [65536 x 64] @ [64 x 2560]
    mma_gemm<5><<<dim3(20, 512), 256, SMEM_BYTES>>>(
        APRE, 64, 64, WPRE,
        /*e0*/ b, /*e1*/ nullptr, /*o0*/ nullptr, /*o1*/ nullptr,
        /*o2h*/ nullptr, /*oh*/ nullptr,
        /*zxp*/ nullptr, /*tgp*/ nullptr, /*Cp*/ nullptr,
        /*inp*/ inputs, /*WtT*/ WtT, /*bT*/ bT);

    for (int t = 0; t < 16; ++t) {
        if (t > 0) {
            // h_{t-1}@[Uh|Wa] + fused gates -> HcH, C, MEMA slot t-1
            mma_gemm<1><<<dim3(20, 32), 256, SMEM_BYTES>>>(
                Ah + (size_t)t * HSLOT, 512, 512, WTb,
                /*e0*/ nullptr, /*e1*/ nullptr, /*o0*/ nullptr, /*o1*/ nullptr,
                /*o2h*/ MEMA16 + (size_t)(t - 1) * HSLOT, /*oh*/ HcH,
                /*zxp*/ ZX16 + (size_t)t * Bn * 2048, /*tgp*/ TG16 + (size_t)t * Bn * 512,
                /*Cp*/ C,
                /*inp*/ nullptr, /*WtT*/ nullptr, /*bT*/ nullptr);
        } else {
            gates0_k<<<8192, 256>>>(ZX16, TG16, C, HcH);
        }
        mma_gemm<2><<<dim3(8, 32), 256, SMEM_BYTES>>>(
            HcH, 512, 512, WT2,
            /*e0*/ ba, /*e1*/ nullptr, /*o0*/ nullptr, /*o1*/ HG,
            /*o2h*/ HBh, /*oh*/ nullptr,
            /*zxp*/ nullptr, /*tgp*/ nullptr, /*Cp*/ nullptr,
            /*inp*/ nullptr, /*WtT*/ nullptr, /*bT*/ nullptr);
        attn_k<<<4096, 256>>>(HBh, va, CXH, t);
        mma_gemm<3><<<dim3(4, 32), 256, SMEM_BYTES>>>(
            CXH, 512, 512, WT3,
            /*e0*/ HG, /*e1*/ bh, /*o0*/ nullptr, /*o1*/ nullptr,
            /*o2h*/ nullptr, /*oh*/ Ah + (size_t)(t + 1) * HSLOT,
            /*zxp*/ nullptr, /*tgp*/ nullptr, /*Cp*/ nullptr,
            /*inp*/ nullptr, /*WtT*/ nullptr, /*bT*/ nullptr);
    }

    mma_gemm<4><<<dim3(2, 32), 256, SMEM_BYTES>>>(
        Ah + (size_t)16 * HSLOT, 512, 512, WTh,
        /*e0*/ b1, /*e1*/ nullptr, /*o0*/ HD1, /*o1*/ nullptr,
        /*o2h*/ nullptr, /*oh*/ nullptr,
        /*zxp*/ nullptr, /*tgp*/ nullptr, /*Cp*/ nullptr,
        /*inp*/ nullptr, /*WtT*/ nullptr, /*bT*/ nullptr);
    head2_k<<<512, 256>>>(HD1, W2, b2, HD2);
    head3_k<<<16, 256>>>(HD2, W3, b3, out);
}

// round 10
// speedup vs baseline: 1.3594x; 1.1367x over previous
#include <cuda_runtime.h>
#include <cuda_fp16.h>
#include <math.h>
#include <stdint.h>

#define Bn 4096
#define HSLOT ((size_t)Bn * 512)
#define STAGE_BYTES 36864
#define SMEM_BYTES (2 * STAGE_BYTES)

// Gate permutation: physical col p (p<2048) <-> logical (gate g, unit j):
//   g = (p>>3)&3, j = ((p>>5)<<3) + (p&7)

// ---------------- device scratch ----------------
__device__ __half g_Ah[(size_t)17 * HSLOT];         // slot j+1 holds h_j (fp16); slot 0 unused
__device__ __half g_APRE[(size_t)65536 * 64];       // [b*16+t][x(63)|t(1)]
__device__ __half g_WTb[(size_t)2560 * 512];        // [Uh(perm) | Wa], n-major
__device__ __half g_WPRE[(size_t)2560 * 64];        // [WxWt(perm) | WxT], n-major
__device__ __half g_WT2[1024 * 512];                // [Wb | Wg]
__device__ __half g_WT3[512 * 512];                 // We
__device__ __half g_WTh[256 * 512];                 // W1
__device__ __half g_ZX16[(size_t)16 * Bn * 2048];   // x@Wx + b + t*Wt (gate-permuted cols)
__device__ __half g_TG16[(size_t)16 * Bn * 512];    // full Tg gate (precomputed)
__device__ __half g_MEMA16[(size_t)15 * HSLOT];     // slot j: h_j @ Wa
__device__ __half g_HcH[(size_t)Bn * 512];
__device__ __half g_HBh[(size_t)Bn * 512];
__device__ __half g_HGh[(size_t)Bn * 512];
__device__ __half g_CXH[(size_t)Bn * 512];
__device__ float g_C[(size_t)Bn * 512];
__device__ float g_HD1[(size_t)Bn * 256];
__device__ float g_HD2[(size_t)Bn * 32];
__device__ float g_s[512];
__device__ float g_sA[512];

__device__ __forceinline__ float sigm(float x) { return 1.f / (1.f + expf(-x)); }
__device__ __forceinline__ float sigmf_(float x) { return __fdividef(1.f, 1.f + __expf(-x)); }
__device__ __forceinline__ float tanh_app(float x) {
    float y; asm("tanh.approx.f32 %0, %1;" : "=f"(y) : "f"(x)); return y;
}

__device__ __forceinline__ uint32_t smem_u32(const void* p) {
    uint32_t a;
    asm("{ .reg .u64 t; cvta.to.shared.u64 t, %1; cvt.u32.u64 %0, t; }" : "=r"(a) : "l"(p));
    return a;
}
__device__ __forceinline__ void ldm4(uint32_t* r, uint32_t a) {
    asm volatile("ldmatrix.sync.aligned.m8n8.x4.shared.b16 {%0,%1,%2,%3}, [%4];"
                 : "=r"(r[0]), "=r"(r[1]), "=r"(r[2]), "=r"(r[3]) : "r"(a));
}
__device__ __forceinline__ void mma16816(float* c, const uint32_t* a, uint32_t b0, uint32_t b1) {
    asm volatile("mma.sync.aligned.m16n8k16.row.col.f32.f16.f16.f32 "
                 "{%0,%1,%2,%3}, {%4,%5,%6,%7}, {%8,%9}, {%0,%1,%2,%3};"
                 : "+f"(c[0]), "+f"(c[1]), "+f"(c[2]), "+f"(c[3])
                 : "r"(a[0]), "r"(a[1]), "r"(a[2]), "r"(a[3]), "r"(b0), "r"(b1));
}
__device__ __forceinline__ void cp16(uint32_t saddr, const void* gptr) {
    asm volatile("cp.async.cg.shared.global [%0], [%1], 16;"
                 :: "r"(saddr), "l"(__cvta_generic_to_global(gptr)) : "memory");
}
__device__ __forceinline__ void cp_commit() {
    asm volatile("cp.async.commit_group;" ::: "memory");
}

// ---------------- prep kernels ----------------
__global__ void prep_weights(const float* __restrict__ Uh, const float* __restrict__ Wx,
                             const float* __restrict__ Wt, const float* __restrict__ Wa,
                             const float* __restrict__ WxT, const float* __restrict__ Wb,
                             const float* __restrict__ Wg, const float* __restrict__ We,
                             const float* __restrict__ W1) {
    int stride = gridDim.x * blockDim.x;
    int t0 = blockIdx.x * blockDim.x + threadIdx.x;
    for (int i = t0; i < 2560 * 512; i += stride) {
        int n = i >> 9, k = i & 511;
        float w;
        if (n < 2048) {
            int g = (n >> 3) & 3, j = ((n >> 5) << 3) + (n & 7);
            w = Uh[(size_t)k * 2048 + g * 512 + j];
        } else {
            w = Wa[(size_t)k * 512 + (n - 2048)];
        }
        g_WTb[i] = __float2half(w);
    }
    for (int i = t0; i < 2560 * 64; i += stride) {
        int n = i >> 6, k = i & 63;
        float w;
        if (n < 2048) {
            int g = (n >> 3) & 3, j = ((n >> 5) << 3) + (n & 7);
            if (k < 63) w = Wx[(size_t)k * 2048 + g * 512 + j];
            else        w = (g < 3) ? Wt[g * 512 + j] : 0.f;
        } else {
            w = (k < 63) ? WxT[(size_t)k * 512 + (n - 2048)] : 0.f;
        }
        g_WPRE[i] = __float2half(w);
    }
    for (int i = t0; i < 1024 * 512; i += stride) {
        int n = i >> 9, k = i & 511;
        float w = (n < 512) ? Wb[(size_t)k * 512 + n] : Wg[(size_t)k * 512 + (n - 512)];
        g_WT2[i] = __float2half(w);
    }
    for (int i = t0; i < 512 * 512; i += stride) {
        int n = i >> 9, k = i & 511;
        g_WT3[i] = __float2half(We[(size_t)k * 512 + n]);
    }
    for (int i = t0; i < 256 * 512; i += stride) {
        int n = i >> 9, k = i & 511;
        g_WTh[i] = __float2half(W1[(size_t)k * 256 + n]);
    }
}

__global__ void prep_s(const float* __restrict__ init_proj) {
    int h = threadIdx.x;
    float s = 0.f;
    for (int f = 0; f < 64; ++f) s += init_proj[f * 512 + h];
    g_s[h] = s;
}

__global__ void prep_sA(const float* __restrict__ Wa) {
    int h = threadIdx.x;
    float acc = 0.f;
    for (int k = 0; k < 512; ++k) acc += g_s[k] * Wa[k * 512 + h];
    g_sA[h] = acc;
}

__global__ void prep_A(const float* __restrict__ inp) {
    int stride = gridDim.x * blockDim.x;
    int t0 = blockIdx.x * blockDim.x + threadIdx.x;
    for (int i = t0; i < 65536 * 64; i += stride) {
        int r = i >> 6, k = i & 63;
        float v = (k < 63) ? inp[(size_t)r * 64 + 1 + k] : inp[(size_t)r * 64];
        g_APRE[i] = __float2half(v);
    }
}

// ---------------- fp16 HMMA GEMM ----------------
// MODE 1: N=2560 [Uh(perm)|Wa]: c<2048 -> FUSED gates -> C, HcH(oh); else MEMA(o2h)
// MODE 2: N=1024 [Wb|Wg]: c<512 -> o2h=HBh(+e0); else oh=HGh (both fp16)
// MODE 3: N=512 We: h=tanh(acc + e0h[row*512+c] + e1[c]) -> oh (next Ah slot)
// MODE 4: N=256 W1: o0 = relu(acc+e0)
// MODE 5: N=2560 pre: rows r=b*16+t; c<2048 -> ZX16(perm); else TG16
template <int MODE>
__global__ __launch_bounds__(256, 2)
void mma_gemm(const __half* __restrict__ A, int lda, int K,
              const __half* __restrict__ Bh,
              const float* __restrict__ e0, const float* __restrict__ e1,
              const __half* __restrict__ e0h,
              float* __restrict__ o0,
              __half* __restrict__ o2h, __half* __restrict__ oh,
              const __half* __restrict__ zxp, const __half* __restrict__ tgp,
              float* __restrict__ Cp,
              const float* __restrict__ inp, const float* __restrict__ WtT,
              const float* __restrict__ bT) {
    extern __shared__ char smem[];
    uint32_t sb = smem_u32(smem);
    const int tid = threadIdx.x;
    const int lane = tid & 31, wid = tid >> 5;
    const int wm = wid & 1, wn = wid >> 1;
    const int gid = lane >> 2, tq = lane & 3;
    const int m0 = blockIdx.y * 128, n0 = blockIdx.x * 128;

    const int kch = K >> 6;

    float acc[4][4][4];
    #pragma unroll
    for (int a = 0; a < 4; ++a)
        #pragma unroll
        for (int b2 = 0; b2 < 4; ++b2)
            #pragma unroll
            for (int c = 0; c < 4; ++c) acc[a][b2][c] = 0.f;

    auto copy_chunk = [&](int ch, int s) {
        int kc = ch << 6;
        uint32_t base = sb + s * STAGE_BYTES;
        #pragma unroll
        for (int i = 0; i < 4; ++i) {
            int lin = tid + (i << 8);
            int r = lin >> 3;
            int c16 = (lin & 7) << 4;
            cp16(base + r * 144 + c16,
                 (const char*)(A + (size_t)(m0 + r) * lda + kc) + c16);
            cp16(base + 18432 + r * 144 + c16,
                 (const char*)(Bh + (size_t)(n0 + r) * K + kc) + c16);
        }
    };

    copy_chunk(0, 0);
    cp_commit();

    const int arow = wm * 64 + (lane & 15);
    const int acol = (lane >> 4) << 4;
    const int brow = wn * 32 + (lane & 7) + ((lane >> 4) << 3);
    const int bcol = ((lane >> 3) & 1) << 4;

    for (int ch = 0; ch < kch; ++ch) {
        if (ch + 1 < kch) {
            copy_chunk(ch + 1, (ch + 1) & 1);
            cp_commit();
            asm volatile("cp.async.wait_group 1;" ::: "memory");
        } else {
            asm volatile("cp.async.wait_group 0;" ::: "memory");
        }
        __syncthreads();

        uint32_t abase = sb + (ch & 1) * STAGE_BYTES;
        uint32_t bbase = abase + 18432;
        #pragma unroll
        for (int k16 = 0; k16 < 4; ++k16) {
            int kb = k16 << 5;
            uint32_t bf[2][4];
            #pragma unroll
            for (int ni2 = 0; ni2 < 2; ++ni2)
                ldm4(bf[ni2], bbase + (brow + ni2 * 16) * 144 + kb + bcol);
            uint32_t af[4][4];
            #pragma unroll
            for (int mi = 0; mi < 4; ++mi)
                ldm4(af[mi], abase + (arow + mi * 16) * 144 + kb + acol);
            #pragma unroll
            for (int ni2 = 0; ni2 < 2; ++ni2)
                #pragma unroll
                for (int mi = 0; mi < 4; ++mi) {
                    mma16816(acc[mi][ni2 * 2],     af[mi], bf[ni2][0], bf[ni2][1]);
                    mma16816(acc[mi][ni2 * 2 + 1], af[mi], bf[ni2][2], bf[ni2][3]);
                }
        }
        __syncthreads();
    }

    // ---- epilogues ----
    if (MODE == 1) {
        if (n0 < 2048) {
            int blk = (n0 + wn * 32) >> 5;
            int j = blk * 8 + (tq << 1);
            #pragma unroll
            for (int mi = 0; mi < 4; ++mi) {
                int mb = m0 + wm * 64 + mi * 16 + gid;
                #pragma unroll
                for (int hf = 0; hf < 2; ++hf) {
                    int r = mb + hf * 8;
                    int ko = hf * 2;
                    const __half* zxr = zxp + (size_t)r * 2048 + blk * 32 + (tq << 1);
                    float2 xi = __half22float2(*(const __half2*)(zxr));
                    float2 xf = __half22float2(*(const __half2*)(zxr + 8));
                    float2 xo = __half22float2(*(const __half2*)(zxr + 16));
                    float2 xc = __half22float2(*(const __half2*)(zxr + 24));
                    float2 tg2 = __half22float2(*(const __half2*)(tgp + (size_t)r * 512 + j));
                    float2 cold = *(float2*)(Cp + (size_t)r * 512 + j);
                    float ch0 = tanh_app(acc[mi][3][ko] + xc.x);
                    float ch1 = tanh_app(acc[mi][3][ko + 1] + xc.y);
                    float c0 = fmaf(sigmf_(acc[mi][1][ko] + xf.x), cold.x,
                                    (sigmf_(acc[mi][0][ko] + xi.x) + tg2.x) * ch0);
                    float c1 = fmaf(sigmf_(acc[mi][1][ko + 1] + xf.y), cold.y,
                                    (sigmf_(acc[mi][0][ko + 1] + xi.y) + tg2.y) * ch1);
                    *(float2*)(Cp + (size_t)r * 512 + j) = make_float2(c0, c1);
                    float h0 = sigmf_(acc[mi][2][ko] + xo.x) * tanh_app(c0);
                    float h1 = sigmf_(acc[mi][2][ko + 1] + xo.y) * tanh_app(c1);
                    *(__half2*)(oh + (size_t)r * 512 + j) = __floats2half2_rn(h0, h1);
                }
            }
        } else {
            #pragma unroll
            for (int mi = 0; mi < 4; ++mi)
                #pragma unroll
                for (int ni = 0; ni < 4; ++ni) {
                    float* cc = acc[mi][ni];
                    int m = m0 + wm * 64 + mi * 16 + gid;
                    int c = n0 + wn * 32 + ni * 8 + (tq << 1) - 2048;
                    *(__half2*)(o2h + (size_t)m * 512 + c) = __floats2half2_rn(cc[0], cc[1]);
                    *(__half2*)(o2h + (size_t)(m + 8) * 512 + c) = __floats2half2_rn(cc[2], cc[3]);
                }
        }
        return;
    }

    auto epi = [&](int m, int c, float x, float y) {
        if (MODE == 2) {
            if (c < 512) {
                *(__half2*)(o2h + (size_t)m * 512 + c) =
                    __floats2half2_rn(x + e0[c], y + e0[c + 1]);
            } else {
                *(__half2*)(oh + (size_t)m * 512 + (c - 512)) = __floats2half2_rn(x, y);
            }
        } else if (MODE == 3) {
            float2 hg = __half22float2(*(const __half2*)(e0h + (size_t)m * 512 + c));
            float h0 = tanh_app(x + hg.x + e1[c]);
            float h1 = tanh_app(y + hg.y + e1[c + 1]);
            *(__half2*)(oh + (size_t)m * 512 + c) = __floats2half2_rn(h0, h1);
        } else if (MODE == 4) {
            *(float2*)(o0 + (size_t)m * 256 + c) =
                make_float2(fmaxf(x + e0[c], 0.f), fmaxf(y + e0[c + 1], 0.f));
        } else {  // MODE 5
            int b_ = m >> 4, t_ = m & 15;
            size_t zr = (size_t)t_ * Bn + b_;
            if (c < 2048) {
                int g = (c >> 3) & 3;
                int j0 = ((c >> 5) << 3) + (c & 7);
                *(__half2*)(g_ZX16 + zr * 2048 + c) =
                    __floats2half2_rn(x + e0[g * 512 + j0], y + e0[g * 512 + j0 + 1]);
            } else {
                int j = c - 2048;
                float tv = inp[(size_t)m * 64];
                float t0v = sigm(x + sigm(tv * WtT[j]) + bT[j]);
                float t1v = sigm(y + sigm(tv * WtT[j + 1]) + bT[j + 1]);
                *(__half2*)(g_TG16 + zr * 512 + j) = __floats2half2_rn(t0v, t1v);
            }
        }
    };

    #pragma unroll
    for (int mi = 0; mi < 4; ++mi) {
        #pragma unroll
        for (int ni = 0; ni < 4; ++ni) {
            float* cc = acc[mi][ni];
            int m = m0 + wm * 64 + mi * 16 + gid;
            int c = n0 + wn * 32 + ni * 8 + (tq << 1);
            epi(m, c, cc[0], cc[1]);
            epi(m + 8, c, cc[2], cc[3]);
        }
    }
}

// ---------------- t=0 gates ----------------
__global__ void gates0_k(const __half* __restrict__ ZX, const __half* __restrict__ TG,
                         float* __restrict__ C, __half* __restrict__ HcH) {
    int idx = blockIdx.x * blockDim.x + threadIdx.x;
    int b = idx >> 9, j = idx & 511;
    int blk = j >> 3, jr = j & 7;
    const __half* zx = ZX + (size_t)b * 2048 + blk * 32 + jr;
    float zi = __half2float(zx[0]);
    float zo = __half2float(zx[16]);
    float zc = __half2float(zx[24]);
    float tg = __half2float(TG[idx]);
    float ch = tanh_app(zc);
    float c = (sigmf_(zi) + tg) * ch;
    C[idx] = c;
    HcH[idx] = __float2half(sigmf_(zo) * tanh_app(c));
}

// ---------------- attention: fully vectorized __half2 path ----------------
// thread tid owns columns 2*tid, 2*tid+1
__global__ void __launch_bounds__(256) attn_k(const __half* __restrict__ HB,
                                              const float* __restrict__ va,
                                              __half* __restrict__ CXH, int t) {
    int b = blockIdx.x, tid = threadIdx.x;
    __shared__ float sred[15][8];
    __shared__ float se[15];
    float2 hb = __half22float2(((const __half2*)(HB + (size_t)b * 512))[tid]);
    float2 va2 = *(const float2*)(va + 2 * tid);
    float2 sA2 = *(const float2*)(g_sA + 2 * tid);
    float2 s2  = *(const float2*)(g_s + 2 * tid);
    int lane = tid & 31, wp = tid >> 5;

    #pragma unroll
    for (int d = 0; d < 15; ++d) {
        int j = t - 15 + d;
        float m0, m1;
        if (j < 0) {
            m0 = sA2.x; m1 = sA2.y;
        } else {
            float2 f = __half22float2(
                ((const __half2*)(g_MEMA16 + (size_t)j * HSLOT + (size_t)b * 512))[tid]);
            m0 = f.x; m1 = f.y;
        }
        float s = va2.x * tanh_app(m0 + hb.x) + va2.y * tanh_app(m1 + hb.y);
        #pragma unroll
        for (int off = 16; off; off >>= 1) s += __shfl_xor_sync(0xffffffffu, s, off);
        if (lane == 0) sred[d][wp] = s;
    }
    __syncthreads();
    if (tid < 15) {
        float e = 0.f;
        #pragma unroll
        for (int w2 = 0; w2 < 8; ++w2) e += sred[tid][w2];
        se[tid] = e;
    }
    __syncthreads();

    float mx = -1e30f;
    #pragma unroll
    for (int d = 0; d < 15; ++d) mx = fmaxf(mx, se[d]);
    float al[15], sum = 0.f;
    #pragma unroll
    for (int d = 0; d < 15; ++d) { al[d] = __expf(se[d] - mx); sum += al[d]; }
    float inv = __fdividef(1.f, sum);
    float c0 = 0.f, c1 = 0.f;
    #pragma unroll
    for (int d = 0; d < 15; ++d) {
        int j = t - 15 + d;
        float a = al[d] * inv;
        float m0, m1;
        if (j < 0) {
            m0 = s2.x; m1 = s2.y;
        } else {
            float2 f = __half22float2(
                ((const __half2*)(g_Ah + (size_t)(j + 1) * HSLOT + (size_t)b * 512))[tid]);
            m0 = f.x; m1 = f.y;
        }
        c0 = fmaf(a, m0, c0);
        c1 = fmaf(a, m1, c1);
    }
    ((__half2*)(CXH + (size_t)b * 512))[tid] = __floats2half2_rn(c0, c1);
}

// ---------------- head layers 2,3 ----------------
__global__ void head2_k(const float* __restrict__ HD1, const float* __restrict__ W2,
                        const float* __restrict__ b2, float* __restrict__ HD2) {
    int warp = (blockIdx.x * blockDim.x + threadIdx.x) >> 5;
    int lane = threadIdx.x & 31;
    if (warp >= Bn) return;
    const float* h = HD1 + (size_t)warp * 256;
    float acc = 0.f;
    for (int k = 0; k < 256; ++k) acc = fmaf(h[k], W2[k * 32 + lane], acc);
    HD2[(size_t)warp * 32 + lane] = fmaxf(acc + b2[lane], 0.f);
}

__global__ void head3_k(const float* __restrict__ HD2, const float* __restrict__ W3,
                        const float* __restrict__ b3, float* __restrict__ out) {
    int b = blockIdx.x * blockDim.x + threadIdx.x;
    if (b >= Bn) return;
    float a0 = b3[0], a1 = b3[1];
    const float* h = HD2 + (size_t)b * 32;
    #pragma unroll
    for (int k = 0; k < 32; ++k) {
        float hv = h[k];
        a0 = fmaf(hv, W3[k * 2 + 0], a0);
        a1 = fmaf(hv, W3[k * 2 + 1], a1);
    }
    float m = fmaxf(a0, a1);
    float e0v = expf(a0 - m), e1v = expf(a1 - m);
    float inv = 1.f / (e0v + e1v);
    out[(size_t)b * 2 + 0] = e0v * inv;
    out[(size_t)b * 2 + 1] = e1v * inv;
}

// ---------------- launcher ----------------
extern "C" void kernel_launch(void* const* d_in, const int* in_sizes, int n_in,
                              void* d_out, int out_size) {
    const float* inputs    = (const float*)d_in[0];
    const float* init_proj = (const float*)d_in[1];
    const float* Wx  = (const float*)d_in[3];
    const float* Uh  = (const float*)d_in[4];
    const float* Wt  = (const float*)d_in[5];
    const float* b   = (const float*)d_in[6];
    const float* WxT = (const float*)d_in[7];
    const float* WtT = (const float*)d_in[8];
    const float* bT  = (const float*)d_in[9];
    const float* Wa  = (const float*)d_in[10];
    const float* Wb  = (const float*)d_in[11];
    const float* va  = (const float*)d_in[12];
    const float* ba  = (const float*)d_in[13];
    const float* We  = (const float*)d_in[14];
    const float* Wg  = (const float*)d_in[15];
    const float* bh  = (const float*)d_in[16];
    const float* W1  = (const float*)d_in[17];
    const float* b1  = (const float*)d_in[18];
    const float* W2  = (const float*)d_in[19];
    const float* b2  = (const float*)d_in[20];
    const float* W3  = (const float*)d_in[21];
    const float* b3  = (const float*)d_in[22];
    float* out = (float*)d_out;

    cudaFuncSetAttribute(mma_gemm<1>, cudaFuncAttributeMaxDynamicSharedMemorySize, SMEM_BYTES);
    cudaFuncSetAttribute(mma_gemm<2>, cudaFuncAttributeMaxDynamicSharedMemorySize, SMEM_BYTES);
    cudaFuncSetAttribute(mma_gemm<3>, cudaFuncAttributeMaxDynamicSharedMemorySize, SMEM_BYTES);
    cudaFuncSetAttribute(mma_gemm<4>, cudaFuncAttributeMaxDynamicSharedMemorySize, SMEM_BYTES);
    cudaFuncSetAttribute(mma_gemm<5>, cudaFuncAttributeMaxDynamicSharedMemorySize, SMEM_BYTES);

    __half *Ah, *APRE, *WTb, *WPRE, *WT2, *WT3, *WTh, *MEMA16, *ZX16, *TG16, *HcH, *HBh, *HGh, *CXH;
    float *C, *HD1, *HD2;
    cudaGetSymbolAddress((void**)&Ah, g_Ah);
    cudaGetSymbolAddress((void**)&APRE, g_APRE);
    cudaGetSymbolAddress((void**)&WTb, g_WTb);
    cudaGetSymbolAddress((void**)&WPRE, g_WPRE);
    cudaGetSymbolAddress((void**)&WT2, g_WT2);
    cudaGetSymbolAddress((void**)&WT3, g_WT3);
    cudaGetSymbolAddress((void**)&WTh, g_WTh);
    cudaGetSymbolAddress((void**)&MEMA16, g_MEMA16);
    cudaGetSymbolAddress((void**)&ZX16, g_ZX16);
    cudaGetSymbolAddress((void**)&TG16, g_TG16);
    cudaGetSymbolAddress((void**)&HcH, g_HcH);
    cudaGetSymbolAddress((void**)&HBh, g_HBh);
    cudaGetSymbolAddress((void**)&HGh, g_HGh);
    cudaGetSymbolAddress((void**)&CXH, g_CXH);
    cudaGetSymbolAddress((void**)&C, g_C);
    cudaGetSymbolAddress((void**)&HD1, g_HD1);
    cudaGetSymbolAddress((void**)&HD2, g_HD2);

    prep_weights<<<1024, 256>>>(Uh, Wx, Wt, Wa, WxT, Wb, Wg, We, W1);
    prep_s<<<1, 512>>>(init_proj);
    prep_sA<<<1, 512>>>(Wa);
    prep_A<<<2048, 256>>>(inputs);

    // pre-GEMM: ZX(perm) + TG for all steps
    mma_gemm<5><<<dim3(20, 512), 256, SMEM_BYTES>>>(
        APRE, 64, 64, WPRE,
        /*e0*/ b, /*e1*/ nullptr, /*e0h*/ nullptr, /*o0*/ nullptr,
        /*o2h*/ nullptr, /*oh*/ nullptr,
        /*zxp*/ nullptr, /*tgp*/ nullptr, /*Cp*/ nullptr,
        /*inp*/ inputs, /*WtT*/ WtT, /*bT*/ bT);

    for (int t = 0; t < 16; ++t) {
        if (t > 0) {
            mma_gemm<1><<<dim3(20, 32), 256, SMEM_BYTES>>>(
                Ah + (size_t)t * HSLOT, 512, 512, WTb,
                /*e0*/ nullptr, /*e1*/ nullptr, /*e0h*/ nullptr, /*o0*/ nullptr,
                /*o2h*/ MEMA16 + (size_t)(t - 1) * HSLOT, /*oh*/ HcH,
                /*zxp*/ ZX16 + (size_t)t * Bn * 2048, /*tgp*/ TG16 + (size_t)t * Bn * 512,
                /*Cp*/ C,
                /*inp*/ nullptr, /*WtT*/ nullptr, /*bT*/ nullptr);
        } else {
            gates0_k<<<8192, 256>>>(ZX16, TG16, C, HcH);
        }
        mma_gemm<2><<<dim3(8, 32), 256, SMEM_BYTES>>>(
            HcH, 512, 512, WT2,
            /*e0*/ ba, /*e1*/ nullptr, /*e0h*/ nullptr, /*o0*/ nullptr,
            /*o2h*/ HBh, /*oh*/ HGh,
            /*zxp*/ nullptr, /*tgp*/ nullptr, /*Cp*/ nullptr,
            /*inp*/ nullptr, /*WtT*/ nullptr, /*bT*/ nullptr);
        attn_k<<<4096, 256>>>(HBh, va, CXH, t);
        mma_gemm<3><<<dim3(4, 32), 256, SMEM_BYTES>>>(
            CXH, 512, 512, WT3,
            /*e0*/ nullptr, /*e1*/ bh, /*e0h*/ HGh, /*o0*/ nullptr,
            /*o2h*/ nullptr, /*oh*/ Ah + (size_t)(t + 1) * HSLOT,
            /*zxp*/ nullptr, /*tgp*/ nullptr, /*Cp*/ nullptr,
            /*inp*/ nullptr, /*WtT*/ nullptr, /*bT*/ nullptr);
    }

    mma_gemm<4><<<dim3(2, 32), 256, SMEM_BYTES>>>(
        Ah + (size_t)16 * HSLOT, 512, 512, WTh,
        /*e0*/ b1, /*e1*/ nullptr, /*e0h*/ nullptr, /*o0*/ HD1,
        /*o2h*/ nullptr, /*oh*/ nullptr,
        /*zxp*/ nullptr, /*tgp*/ nullptr, /*Cp*/ nullptr,
        /*inp*/ nullptr, /*WtT*/ nullptr, /*bT*/ nullptr);
    head2_k<<<512, 256>>>(HD1, W2, b2, HD2);
    head3_k<<<16, 256>>>(HD2, W3, b3, out);
}